// round 9
// baseline (speedup 1.0000x reference)
#include <cuda_runtime.h>
#include <cuda_fp16.h>
#include <stdint.h>
#include <math.h>

// ---------------- problem constants ----------------
#define Bb   2
#define Ll   1024
#define HIDv 1024
#define NHh  4
#define DKk  256
#define NCc  32
#define CHh  32
#define BLr  2048
#define GHh  512

extern __shared__ char dynsm[];

// ---------------- scratch ----------------
__device__ float g_qlin[BLr * HIDv];
__device__ float g_klin[BLr * HIDv];
__device__ float g_vlin[BLr * HIDv];
__device__ float g_q[BLr * HIDv];
__device__ float g_k[BLr * HIDv];
__device__ float g_v[BLr * HIDv];
__device__ float g_beta[BLr * NHh];
__device__ float g_qn[BLr * HIDv];
__device__ float g_kn[BLr * HIDv];
__device__ float g_u[BLr * HIDv];
__device__ float g_w[BLr * HIDv];
__device__ float g_attn[Bb * NHh * NCc * CHh * CHh];
__device__ float g_P[BLr * NHh * 4 * DKk];
__device__ float g_stats[BLr * NHh * 12];
__device__ float g_ssum[12 * GHh];
__device__ float g_hid1[BLr * GHh];
__device__ float g_bpart[BLr * NHh * GHh];
__device__ float g_omix[BLr * HIDv];

__device__ __half g_xh[BLr * HIDv];
__device__ __half g_Ph[BLr * NHh * 4 * DKk];
__device__ __half g_oh[BLr * HIDv];
__device__ __half g_Wqh[HIDv * HIDv], g_Wql[HIDv * HIDv];
__device__ __half g_Wkh[HIDv * HIDv], g_Wkl[HIDv * HIDv];
__device__ __half g_Wvh[HIDv * HIDv], g_Wvl[HIDv * HIDv];
__device__ __half g_Woh[HIDv * HIDv], g_Wol[HIDv * HIDv];
__device__ __half g_g1ah[GHh * HIDv], g_g1al[GHh * HIDv];
__device__ __half g_g1bh[GHh * HIDv], g_g1bl[GHh * HIDv];

// ---------------- PTX helpers ----------------
__device__ __forceinline__ uint32_t smem_u32(const void* p) {
    uint32_t a;
    asm("{ .reg .u64 t; cvta.to.shared.u64 t, %1; cvt.u32.u64 %0, t; }" : "=r"(a) : "l"(p));
    return a;
}
__device__ __forceinline__ void ldsm_x4(uint32_t* r, uint32_t addr) {
    asm volatile("ldmatrix.sync.aligned.m8n8.x4.shared.b16 {%0,%1,%2,%3}, [%4];"
                 : "=r"(r[0]), "=r"(r[1]), "=r"(r[2]), "=r"(r[3]) : "r"(addr));
}
__device__ __forceinline__ void mma16816h(float* d, const uint32_t* a, const uint32_t* b) {
    asm volatile(
        "mma.sync.aligned.m16n8k16.row.col.f32.f16.f16.f32 "
        "{%0,%1,%2,%3}, {%4,%5,%6,%7}, {%8,%9}, {%0,%1,%2,%3};"
        : "+f"(d[0]), "+f"(d[1]), "+f"(d[2]), "+f"(d[3])
        : "r"(a[0]), "r"(a[1]), "r"(a[2]), "r"(a[3]), "r"(b[0]), "r"(b[1]));
}

// ---------------- fp16x2 HMMA GEMM: C[M,N] = A[M,K] @ Bt[N,K]^T ----------------
#define LDAh 40
#define TILEB (128 * LDAh * 2)
#define GEMM_SMEM (2 * 3 * TILEB)     // 61440 B

__global__ __launch_bounds__(256, 1) void gemm_fp16x2(
    const __half* __restrict__ A,
    const __half* __restrict__ Bh, const __half* __restrict__ Bl,
    float* __restrict__ C, int M, int N, int K) {
    char* smc = dynsm;
    uint32_t sbase = smem_u32(smc);
    int t = threadIdx.x;
    int lane = t & 31;
    int wid = t >> 5;
    int wm = wid & 1;
    int wn = wid >> 1;
    int m0 = blockIdx.y * 128;
    int n0 = blockIdx.x * 128;

    float acc[4][4][4];
#pragma unroll
    for (int i = 0; i < 4; i++)
#pragma unroll
        for (int j = 0; j < 4; j++)
#pragma unroll
            for (int c = 0; c < 4; c++) acc[i][j][c] = 0.f;

    uint4 rg[6];
    int ldrow = t >> 2;
    int ldq = t & 3;

    int a_off = ((wm * 64 + (lane & 15)) * LDAh + ((lane >> 4) << 3)) * 2;
    int b_off = ((wn * 32 + (lane & 7) + ((lane >> 4) << 3)) * LDAh + (((lane >> 3) & 1) << 3)) * 2;

    const int S = K / 32;

#pragma unroll
    for (int i = 0; i < 2; i++) {
        int row = ldrow + i * 64;
        size_t ga = (size_t)(m0 + row) * K + ldq * 8;
        size_t gb = (size_t)(n0 + row) * K + ldq * 8;
        rg[i]     = *(const uint4*)(A + ga);
        rg[2 + i] = *(const uint4*)(Bh + gb);
        rg[4 + i] = *(const uint4*)(Bl + gb);
    }
#pragma unroll
    for (int i = 0; i < 2; i++) {
        int row = ldrow + i * 64;
        int off = (row * LDAh + ldq * 8) * 2;
        *(uint4*)(smc + off)             = rg[i];
        *(uint4*)(smc + TILEB + off)     = rg[2 + i];
        *(uint4*)(smc + 2 * TILEB + off) = rg[4 + i];
    }
    __syncthreads();

    for (int s = 0; s < S; s++) {
        int cur = s & 1;
        if (s + 1 < S) {
            int k0 = (s + 1) * 32;
#pragma unroll
            for (int i = 0; i < 2; i++) {
                int row = ldrow + i * 64;
                size_t ga = (size_t)(m0 + row) * K + k0 + ldq * 8;
                size_t gb = (size_t)(n0 + row) * K + k0 + ldq * 8;
                rg[i]     = *(const uint4*)(A + ga);
                rg[2 + i] = *(const uint4*)(Bh + gb);
                rg[4 + i] = *(const uint4*)(Bl + gb);
            }
        }

        uint32_t sb = sbase + cur * 3 * TILEB;
#pragma unroll
        for (int kk = 0; kk < 32; kk += 16) {
            uint32_t ah[4][4], bhf[2][4], blf[2][4];
#pragma unroll
            for (int mi = 0; mi < 4; mi++)
                ldsm_x4(ah[mi], sb + a_off + mi * 16 * LDAh * 2 + kk * 2);
#pragma unroll
            for (int nb = 0; nb < 2; nb++)
                ldsm_x4(bhf[nb], sb + TILEB + b_off + nb * 16 * LDAh * 2 + kk * 2);
#pragma unroll
            for (int nb = 0; nb < 2; nb++)
                ldsm_x4(blf[nb], sb + 2 * TILEB + b_off + nb * 16 * LDAh * 2 + kk * 2);
#pragma unroll
            for (int mi = 0; mi < 4; mi++)
#pragma unroll
                for (int nb = 0; nb < 2; nb++) {
                    mma16816h(acc[mi][nb * 2 + 0], ah[mi], &bhf[nb][0]);
                    mma16816h(acc[mi][nb * 2 + 1], ah[mi], &bhf[nb][2]);
                }
#pragma unroll
            for (int mi = 0; mi < 4; mi++)
#pragma unroll
                for (int nb = 0; nb < 2; nb++) {
                    mma16816h(acc[mi][nb * 2 + 0], ah[mi], &blf[nb][0]);
                    mma16816h(acc[mi][nb * 2 + 1], ah[mi], &blf[nb][2]);
                }
        }

        if (s + 1 < S) {
            char* bb = smc + ((s + 1) & 1) * 3 * TILEB;
#pragma unroll
            for (int i = 0; i < 2; i++) {
                int row = ldrow + i * 64;
                int off = (row * LDAh + ldq * 8) * 2;
                *(uint4*)(bb + off)             = rg[i];
                *(uint4*)(bb + TILEB + off)     = rg[2 + i];
                *(uint4*)(bb + 2 * TILEB + off) = rg[4 + i];
            }
        }
        __syncthreads();
    }

    int frow = lane >> 2;
    int fcol = (lane & 3) * 2;
#pragma unroll
    for (int mi = 0; mi < 4; mi++) {
#pragma unroll
        for (int ni = 0; ni < 4; ni++) {
            int row = m0 + wm * 64 + mi * 16 + frow;
            int col = n0 + wn * 32 + ni * 8 + fcol;
            *(float2*)(C + (size_t)row * N + col) = make_float2(acc[mi][ni][0], acc[mi][ni][1]);
            *(float2*)(C + (size_t)(row + 8) * N + col) = make_float2(acc[mi][ni][2], acc[mi][ni][3]);
        }
    }
}

// ---------------- fp32 -> fp16 convert ----------------
__global__ void tohalf_kernel(const float* __restrict__ src,
                              __half* __restrict__ dst, int n) {
    int i = blockIdx.x * 256 + threadIdx.x;
    if (i < n) dst[i] = __float2half(src[i]);
}

// src [K][N] fp32 -> dst [N][K] fp16 (hi/lo)
__global__ void split_transpose_kernel(const float* __restrict__ src,
                                       __half* __restrict__ hi,
                                       __half* __restrict__ lo,
                                       int K, int N) {
    __shared__ float tile[32][33];
    int k0 = blockIdx.y * 32;
    int n0 = blockIdx.x * 32;
    int tx = threadIdx.x & 31;
    int ty = threadIdx.x >> 5;
    for (int r = ty; r < 32; r += 8) tile[r][tx] = src[(size_t)(k0 + r) * N + n0 + tx];
    __syncthreads();
    for (int r = ty; r < 32; r += 8) {
        float v = tile[tx][r];
        __half h = __float2half(v);
        size_t o = (size_t)(n0 + r) * K + k0 + tx;
        hi[o] = h;
        lo[o] = __float2half(v - __half2float(h));
    }
}

// 4 fused 1024x1024 weight split-transposes
__global__ void split_transpose4_kernel(const float* __restrict__ s0, const float* __restrict__ s1,
                                        const float* __restrict__ s2, const float* __restrict__ s3,
                                        __half* __restrict__ h0, __half* __restrict__ h1,
                                        __half* __restrict__ h2, __half* __restrict__ h3,
                                        __half* __restrict__ l0, __half* __restrict__ l1,
                                        __half* __restrict__ l2, __half* __restrict__ l3) {
    __shared__ float tile[32][33];
    int z = blockIdx.z;
    const float* src = (z == 0) ? s0 : (z == 1) ? s1 : (z == 2) ? s2 : s3;
    __half* hi = (z == 0) ? h0 : (z == 1) ? h1 : (z == 2) ? h2 : h3;
    __half* lo = (z == 0) ? l0 : (z == 1) ? l1 : (z == 2) ? l2 : l3;
    int k0 = blockIdx.y * 32;
    int n0 = blockIdx.x * 32;
    int tx = threadIdx.x & 31;
    int ty = threadIdx.x >> 5;
    for (int r = ty; r < 32; r += 8) tile[r][tx] = src[(size_t)(k0 + r) * 1024 + n0 + tx];
    __syncthreads();
    for (int r = ty; r < 32; r += 8) {
        float v = tile[tx][r];
        __half h = __float2half(v);
        size_t o = (size_t)(n0 + r) * 1024 + k0 + tx;
        hi[o] = h;
        lo[o] = __float2half(v - __half2float(h));
    }
}

// ---------------- beta = sigmoid(x @ Wb) ----------------
__global__ void beta_kernel(const float* __restrict__ x, const float* __restrict__ Wb) {
    int gw   = (blockIdx.x << 3) + (threadIdx.x >> 5);
    int lane = threadIdx.x & 31;
    const float* xr = x + (size_t)gw * HIDv;
    float a0 = 0.f, a1 = 0.f, a2 = 0.f, a3 = 0.f;
    for (int r = lane; r < HIDv; r += 32) {
        float xv = xr[r];
        const float* wb = Wb + r * 4;
        a0 += xv * wb[0]; a1 += xv * wb[1]; a2 += xv * wb[2]; a3 += xv * wb[3];
    }
    for (int o = 16; o; o >>= 1) {
        a0 += __shfl_xor_sync(0xffffffffu, a0, o);
        a1 += __shfl_xor_sync(0xffffffffu, a1, o);
        a2 += __shfl_xor_sync(0xffffffffu, a2, o);
        a3 += __shfl_xor_sync(0xffffffffu, a3, o);
    }
    if (!lane) {
        float* bp = &g_beta[gw * 4];
        bp[0] = 1.f / (1.f + expf(-a0));
        bp[1] = 1.f / (1.f + expf(-a1));
        bp[2] = 1.f / (1.f + expf(-a2));
        bp[3] = 1.f / (1.f + expf(-a3));
    }
}

// ---------------- fused: 3x causal depthwise conv (k=4) + silu ----------------
__global__ void conv3_kernel(const float* __restrict__ in0, const float* __restrict__ w0, float* __restrict__ out0,
                             const float* __restrict__ in1, const float* __restrict__ w1, float* __restrict__ out1,
                             const float* __restrict__ in2, const float* __restrict__ w2, float* __restrict__ out2) {
    int which = blockIdx.x >> 13;
    int bx = blockIdx.x & 8191;
    const float* in = which == 0 ? in0 : (which == 1 ? in1 : in2);
    const float* w  = which == 0 ? w0  : (which == 1 ? w1  : w2);
    float* out      = which == 0 ? out0 : (which == 1 ? out1 : out2);
    int idx = bx * 256 + threadIdx.x;
    int c = idx & 1023;
    int l = (idx >> 10) & 1023;
    int b = idx >> 20;
    const float* wc = w + c * 4;
    float acc = 0.f;
#pragma unroll
    for (int j = 0; j < 4; j++) {
        int ls = l - 3 + j;
        if (ls >= 0) acc += in[((size_t)b * Ll + ls) * HIDv + c] * wc[j];
    }
    out[idx] = acc / (1.f + expf(-acc));
}

// ---------------- fused FIR: short (K=3), long (K=31), v copy ----------------
__global__ void fir_both_kernel(const float* __restrict__ v,
                                const float* __restrict__ fs,
                                const float* __restrict__ fl) {
    int idx = blockIdx.x * 256 + threadIdx.x;
    int d = idx & 255;
    int h = (idx >> 8) & 3;
    int l = (idx >> 10) & 1023;
    int b = idx >> 20;
    const float* fls = fl + (h * 256 + d) * 31;
    const float* fss = fs + (h * 256 + d) * 3;
    float accL = 0.f, accS = 0.f, vcur = 0.f;
    for (int j = 0; j < 31; j++) {
        int ls = l - 30 + j;
        if (ls >= 0) {
            float vv = v[(((size_t)b * Ll + ls) * NHh + h) * 256 + d];
            accL += vv * fls[j];
            if (j >= 28) accS += vv * fss[j - 28];
            if (j == 30) vcur = vv;
        }
    }
    size_t row = ((size_t)b * Ll + l) * NHh + h;
    g_P[(row * 4 + 0) * 256 + d] = accS;
    g_P[(row * 4 + 1) * 256 + d] = accL;
    g_P[(row * 4 + 3) * 256 + d] = vcur;
}

// ---------------- delta pre ----------------
__global__ void delta_pre_kernel() {
    float* smf = (float*)dynsm;
    float* qs  = smf;
    float* kn  = qs + 8224;
    float* vb  = kn + 8224;
    float* Am  = vb + 8224;
    float* Tm  = Am + 1024;
    float* bet = Tm + 1056;
    float* rsq = bet + 32;
    float* rsk = rsq + 32;

    int t  = threadIdx.x;
    int n  = blockIdx.x & 31;
    int bh = blockIdx.x >> 5;
    int h  = bh & 3;
    int b  = bh >> 2;
    int l0 = n * CHh;
    size_t gbase = (((size_t)b * Ll + l0) * NHh + h) * 256;
    size_t obase = ((((size_t)b * NHh + h) * NCc + n) * CHh) * 256;

    for (int idx = t; idx < CHh * 256; idx += 256) {
        int c = idx >> 8;
        int d = idx & 255;
        size_t off = gbase + (size_t)c * (NHh * 256) + d;
        qs[c * 257 + d] = g_q[off];
        kn[c * 257 + d] = g_k[off];
        vb[c * 257 + d] = g_v[off];
    }
    if (t < CHh) bet[t] = g_beta[((size_t)b * Ll + l0 + t) * NHh + h];
    __syncthreads();

    int lane = t & 31;
    int wid = t >> 5;
    for (int r = wid; r < CHh; r += 8) {
        float sq = 0.f, sk = 0.f;
        for (int d = lane; d < 256; d += 32) {
            float a = qs[r * 257 + d]; sq += a * a;
            float c2 = kn[r * 257 + d]; sk += c2 * c2;
        }
        for (int o = 16; o; o >>= 1) {
            sq += __shfl_xor_sync(0xffffffffu, sq, o);
            sk += __shfl_xor_sync(0xffffffffu, sk, o);
        }
        if (!lane) { rsq[r] = rsqrtf(sq + 1e-6f); rsk[r] = rsqrtf(sk + 1e-6f); }
    }
    __syncthreads();

    for (int idx = t; idx < CHh * 256; idx += 256) {
        int c = idx >> 8;
        int d = idx & 255;
        float qv = qs[c * 257 + d] * rsq[c]; qs[c * 257 + d] = qv; g_qn[obase + idx] = qv;
        float kv = kn[c * 257 + d] * rsk[c]; kn[c * 257 + d] = kv; g_kn[obase + idx] = kv;
        vb[c * 257 + d] *= bet[c];
    }
    __syncthreads();

    size_t abase = ((((size_t)b * NHh + h) * NCc + n) << 10);
    for (int p = t; p < 1024; p += 256) {
        int i = p >> 5;
        int jj = p & 31;
        float dq = 0.f, dk2 = 0.f;
        if (jj <= i) {
            const float* qi = &qs[i * 257];
            const float* kj = &kn[jj * 257];
            for (int d = 0; d < 256; d++) dq += qi[d] * kj[d];
        }
        if (jj < i) {
            const float* ki = &kn[i * 257];
            const float* kj = &kn[jj * 257];
            for (int d = 0; d < 256; d++) dk2 += ki[d] * kj[d];
        }
        Am[p] = (jj < i) ? (-bet[i] * dk2) : 0.f;
        g_attn[abase + p] = (jj <= i) ? dq : 0.f;
    }
    __syncthreads();

    if (t < 32) {
        Tm[t] = (t == 0) ? 1.f : 0.f;
        for (int i = 1; i < 32; i++) {
            float acc = (i == t) ? 1.f : 0.f;
            for (int m = 0; m < i; m++) acc += Am[i * 32 + m] * Tm[m * 33 + t];
            Tm[i * 33 + t] = acc;
        }
    }
    __syncthreads();

    {
        int d = t;
        for (int r = 0; r < 32; r++) {
            float au = 0.f, aw = 0.f;
            const float* Tr = &Tm[r * 33];
            for (int m = 0; m <= r; m++) {
                float tv = Tr[m];
                au += tv * vb[m * 257 + d];
                aw += tv * bet[m] * kn[m * 257 + d];
            }
            g_u[obase + r * 256 + d] = au;
            g_w[obase + r * 256 + d] = aw;
        }
    }
}

// ---------------- serial chunk scan ----------------
#define KST 272
__global__ void scan_kernel() {
    float* smf = (float*)dynsm;
    float* S  = smf;
    float* qn = S + 4352;
    float* kn = qn + 8704;
    float* wS = kn + 8704;
    float* un = wS + 8704;
    float* uu = un + 544;
    float* at = uu + 512;

    int t = threadIdx.x;
    int s_idx = blockIdx.x & 15;
    int bh = blockIdx.x >> 4;
    int h = bh & 3;
    int b = bh >> 2;
    int j0 = s_idx * 16;

    for (int i = t; i < 4352; i += 256) S[i] = 0.f;
    __syncthreads();

    int j = t & 15;
    int cg = t >> 4;
    int c0 = cg * 2;
    int c1 = c0 + 1;

    for (int n = 0; n < NCc; n++) {
        size_t base = ((((size_t)b * NHh + h) * NCc + n) * CHh) * 256;
        for (int idx = t; idx < 32 * 64; idx += 256) {
            int c = idx >> 6;
            int dq = (idx & 63) << 2;
            *(float4*)(&qn[c * KST + dq]) = *(const float4*)(&g_qn[base + c * 256 + dq]);
            *(float4*)(&kn[c * KST + dq]) = *(const float4*)(&g_kn[base + c * 256 + dq]);
            *(float4*)(&wS[c * KST + dq]) = *(const float4*)(&g_w [base + c * 256 + dq]);
        }
        for (int idx = t; idx < 512; idx += 256) {
            int c = idx >> 4;
            int jj = idx & 15;
            uu[idx] = g_u[base + c * 256 + j0 + jj];
        }
        size_t abase = ((((size_t)b * NHh + h) * NCc + n) << 10);
        for (int idx = t; idx < 1024; idx += 256) {
            int c = idx >> 5;
            int cp = idx & 31;
            at[c * 33 + cp] = g_attn[abase + idx];
        }
        __syncthreads();

        float a0 = uu[c0 * 16 + j];
        float a1 = uu[c1 * 16 + j];
        float o0 = 0.f, o1 = 0.f;
        const float* w0 = &wS[c0 * KST];
        const float* w1 = &wS[c1 * KST];
        const float* q0 = &qn[c0 * KST];
        const float* q1 = &qn[c1 * KST];
#pragma unroll 8
        for (int d4 = 0; d4 < 64; d4++) {
            int d = d4 << 2;
            float4 wv0 = *(const float4*)(&w0[d]);
            float4 wv1 = *(const float4*)(&w1[d]);
            float4 qv0 = *(const float4*)(&q0[d]);
            float4 qv1 = *(const float4*)(&q1[d]);
            float s0 = S[(d + 0) * 17 + j];
            float s1 = S[(d + 1) * 17 + j];
            float s2 = S[(d + 2) * 17 + j];
            float s3 = S[(d + 3) * 17 + j];
            a0 -= wv0.x * s0 + wv0.y * s1 + wv0.z * s2 + wv0.w * s3;
            a1 -= wv1.x * s0 + wv1.y * s1 + wv1.z * s2 + wv1.w * s3;
            o0 += qv0.x * s0 + qv0.y * s1 + qv0.z * s2 + qv0.w * s3;
            o1 += qv1.x * s0 + qv1.y * s1 + qv1.z * s2 + qv1.w * s3;
        }
        un[c0 * 17 + j] = a0;
        un[c1 * 17 + j] = a1;
        __syncthreads();

        for (int cp = 0; cp <= c0; cp++) o0 += at[c0 * 33 + cp] * un[cp * 17 + j];
        for (int cp = 0; cp <= c1; cp++) o1 += at[c1 * 33 + cp] * un[cp * 17 + j];
        {
            int l = n * CHh;
            size_t r0 = (((size_t)b * Ll + l + c0) * NHh + h) * 4 + 2;
            size_t r1 = (((size_t)b * Ll + l + c1) * NHh + h) * 4 + 2;
            g_P[r0 * 256 + j0 + j] = o0;
            g_P[r1 * 256 + j0 + j] = o1;
        }

#pragma unroll
        for (int blk = 0; blk < 4; blk++) {
            int d0 = cg * 16 + blk * 4;
            float s0 = S[(d0 + 0) * 17 + j];
            float s1 = S[(d0 + 1) * 17 + j];
            float s2 = S[(d0 + 2) * 17 + j];
            float s3 = S[(d0 + 3) * 17 + j];
            for (int c = 0; c < 32; c++) {
                float u = un[c * 17 + j];
                float4 kv = *(const float4*)(&kn[c * KST + d0]);
                s0 += kv.x * u; s1 += kv.y * u; s2 += kv.z * u; s3 += kv.w * u;
            }
            S[(d0 + 0) * 17 + j] = s0;
            S[(d0 + 1) * 17 + j] = s1;
            S[(d0 + 2) * 17 + j] = s2;
            S[(d0 + 3) * 17 + j] = s3;
        }
        __syncthreads();
    }
}

// ---------------- per-branch stats ----------------
__global__ void stats_kernel() {
    int gw = (blockIdx.x << 3) + (threadIdx.x >> 5);
    int lane = threadIdx.x & 31;
    int row = gw >> 2;
    int jb = gw & 3;
    const float* p = &g_P[((size_t)row * 4 + jb) << 8];
    float smv = 0.f, sq = 0.f, mx = -3.4e38f;
    for (int d = lane; d < 256; d += 32) {
        float v = p[d];
        smv += v; sq += v * v; mx = fmaxf(mx, v);
    }
    for (int o = 16; o; o >>= 1) {
        smv += __shfl_xor_sync(0xffffffffu, smv, o);
        sq  += __shfl_xor_sync(0xffffffffu, sq, o);
        mx   = fmaxf(mx, __shfl_xor_sync(0xffffffffu, mx, o));
    }
    if (!lane) {
        float* s = &g_stats[(size_t)row * 12 + jb * 3];
        s[0] = smv * (1.f / 256.f);
        s[1] = sqrtf(fmaxf(sq * (1.f / 256.f), 1e-8f));
        s[2] = mx;
    }
}

// ---------------- gW1 stat-block column sums ----------------
__global__ void ssum_kernel(const float* __restrict__ gW1) {
    int idx = blockIdx.x * 256 + threadIdx.x;
    int s12 = idx / GHh;
    int nn = idx % GHh;
    float a = 0.f;
    const float* base = gW1 + (size_t)(1024 + s12 * 256) * GHh + nn;
    for (int r = 0; r < 256; r++) a += base[(size_t)r * GHh];
    g_ssum[idx] = a;
}

// ---------------- gate finalize ----------------
__global__ void gate_final_kernel(const float* __restrict__ gb1,
                                  const float* __restrict__ gW2,
                                  const float* __restrict__ gb2,
                                  const float* __restrict__ temp,
                                  const float* __restrict__ epsf,
                                  const float* __restrict__ onw) {
    __shared__ float mid[GHh];
    __shared__ float st[12];
    __shared__ float w4[4];
    __shared__ float red[256];
    int row = blockIdx.x;
    int t = threadIdx.x;
    int h = row & 3;
    int bl = row >> 2;

    if (t < 12) st[t] = g_stats[(size_t)row * 12 + t];
    __syncthreads();

    for (int nn = t; nn < GHh; nn += 256) {
        float val = g_hid1[(size_t)bl * GHh + nn] + g_bpart[(size_t)row * GHh + nn] + gb1[nn];
#pragma unroll
        for (int s12 = 0; s12 < 12; s12++) val += st[s12] * g_ssum[s12 * GHh + nn];
        mid[nn] = 0.5f * val * (1.f + erff(val * 0.70710678118654752f));
    }
    __syncthreads();

    {
        int o = t & 3;
        float p = 0.f;
        for (int nidx = t >> 2; nidx < GHh; nidx += 64) p += mid[nidx] * gW2[nidx * 4 + o];
        red[t] = p;
    }
    __syncthreads();
    if (t < 4) {
        float lg = gb2[t];
        for (int g = 0; g < 64; g++) lg += red[g * 4 + t];
        red[t] = lg;
    }
    __syncthreads();
    if (t == 0) {
        float tc = fminf(fmaxf(temp[h], 0.2f), 10.f);
        float l0 = red[0] / tc, l1 = red[1] / tc, l2 = red[2] / tc, l3 = red[3] / tc;
        float mx = fmaxf(fmaxf(l0, l1), fmaxf(l2, l3));
        float e0 = expf(l0 - mx), e1 = expf(l1 - mx), e2 = expf(l2 - mx), e3 = expf(l3 - mx);
        float s = e0 + e1 + e2 + e3;
        float w0 = e0 / s, w1 = e1 / s, w2 = e2 / s, w3 = e3 / s;
        float f0 = fminf(fmaxf(epsf[h * 4 + 0], 1e-7f), 0.1f);
        float f1 = fminf(fmaxf(epsf[h * 4 + 1], 1e-7f), 0.1f);
        float f2 = fminf(fmaxf(epsf[h * 4 + 2], 1e-7f), 0.1f);
        float f3 = fminf(fmaxf(epsf[h * 4 + 3], 1e-7f), 0.1f);
        w0 = fmaxf(w0, f0); w1 = fmaxf(w1, f1); w2 = fmaxf(w2, f2); w3 = fmaxf(w3, f3);
        float s2 = w0 + w1 + w2 + w3;
        w4[0] = w0 / s2; w4[1] = w1 / s2; w4[2] = w2 / s2; w4[3] = w3 / s2;
    }
    __syncthreads();

    float od = 0.f;
#pragma unroll
    for (int jj = 0; jj < 4; jj++) od += w4[jj] * g_P[((size_t)row * 4 + jj) * 256 + t];
    red[t] = od * od;
    __syncthreads();
    for (int s = 128; s > 0; s >>= 1) {
        if (t < s) red[t] += red[t + s];
        __syncthreads();
    }
    float ms = red[0] * (1.f / 256.f);
    g_omix[(size_t)bl * HIDv + h * 256 + t] = od * rsqrtf(ms + 1e-5f) * onw[t];
}

// ---------------- host launcher ----------------
static const int PRE_SMEM  = 26848 * 4;
static const int SCAN_SMEM = 32576 * 4;

extern "C" void kernel_launch(void* const* d_in, const int* in_sizes, int n_in,
                              void* d_out, int out_size) {
    const float *x = 0, *Wq = 0, *Wk = 0, *Wv = 0, *Wb = 0, *qc = 0, *kc = 0, *vc = 0;
    const float *firs = 0, *firl = 0, *gW1 = 0, *gb1 = 0, *gW2 = 0, *gb2 = 0;
    const float *temp = 0, *epsf = 0, *onw = 0, *Wo = 0;
    int occ1M = 0, occ4k = 0, occ4 = 0;
    for (int i = 0; i < n_in; i++) {
        const float* p = (const float*)d_in[i];
        switch (in_sizes[i]) {
            case 2097152: x = p; break;
            case 1048576:
                if (occ1M == 0) Wq = p; else if (occ1M == 1) Wk = p;
                else if (occ1M == 2) Wv = p; else Wo = p;
                occ1M++; break;
            case 4096:
                if (occ4k == 0) Wb = p; else if (occ4k == 1) qc = p;
                else if (occ4k == 2) kc = p; else vc = p;
                occ4k++; break;
            case 2621440: gW1 = p; break;
            case 512:     gb1 = p; break;
            case 2048:    gW2 = p; break;
            case 4:       if (occ4 == 0) gb2 = p; else temp = p; occ4++; break;
            case 16:      epsf = p; break;
            case 256:     onw = p; break;
            case 3072:    firs = p; break;
            case 31744:   firl = p; break;
            default: break;
        }
    }

    float *p_qlin, *p_klin, *p_vlin, *p_q, *p_k, *p_v, *p_P, *p_hid1, *p_bpart, *p_omix;
    cudaGetSymbolAddress((void**)&p_qlin, g_qlin);
    cudaGetSymbolAddress((void**)&p_klin, g_klin);
    cudaGetSymbolAddress((void**)&p_vlin, g_vlin);
    cudaGetSymbolAddress((void**)&p_q, g_q);
    cudaGetSymbolAddress((void**)&p_k, g_k);
    cudaGetSymbolAddress((void**)&p_v, g_v);
    cudaGetSymbolAddress((void**)&p_P, g_P);
    cudaGetSymbolAddress((void**)&p_hid1, g_hid1);
    cudaGetSymbolAddress((void**)&p_bpart, g_bpart);
    cudaGetSymbolAddress((void**)&p_omix, g_omix);

    __half *xh, *Ph, *oh;
    __half *Wqh, *Wql, *Wkh, *Wkl, *Wvh, *Wvl, *Woh, *Wol, *g1ah, *g1al, *g1bh, *g1bl;
    cudaGetSymbolAddress((void**)&xh, g_xh);
    cudaGetSymbolAddress((void**)&Ph, g_Ph);
    cudaGetSymbolAddress((void**)&oh, g_oh);
    cudaGetSymbolAddress((void**)&Wqh, g_Wqh);   cudaGetSymbolAddress((void**)&Wql, g_Wql);
    cudaGetSymbolAddress((void**)&Wkh, g_Wkh);   cudaGetSymbolAddress((void**)&Wkl, g_Wkl);
    cudaGetSymbolAddress((void**)&Wvh, g_Wvh);   cudaGetSymbolAddress((void**)&Wvl, g_Wvl);
    cudaGetSymbolAddress((void**)&Woh, g_Woh);   cudaGetSymbolAddress((void**)&Wol, g_Wol);
    cudaGetSymbolAddress((void**)&g1ah, g_g1ah); cudaGetSymbolAddress((void**)&g1al, g_g1al);
    cudaGetSymbolAddress((void**)&g1bh, g_g1bh); cudaGetSymbolAddress((void**)&g1bl, g_g1bl);

    cudaFuncSetAttribute(delta_pre_kernel, cudaFuncAttributeMaxDynamicSharedMemorySize, PRE_SMEM);
    cudaFuncSetAttribute(scan_kernel, cudaFuncAttributeMaxDynamicSharedMemorySize, SCAN_SMEM);
    cudaFuncSetAttribute(gemm_fp16x2, cudaFuncAttributeMaxDynamicSharedMemorySize, GEMM_SMEM);

    // side streams + events (created once; capture-fork pattern)
    static cudaStream_t s1 = 0, s2 = 0, s3 = 0;
    static cudaEvent_t evStart = 0, evX = 0, evW = 0, evBeta = 0, evK = 0, evV = 0,
                       evConv = 0, evFir = 0, evScan = 0, evS1 = 0, evStats = 0;
    if (!s1) {
        cudaStreamCreateWithFlags(&s1, cudaStreamNonBlocking);
        cudaStreamCreateWithFlags(&s2, cudaStreamNonBlocking);
        cudaStreamCreateWithFlags(&s3, cudaStreamNonBlocking);
        cudaEventCreateWithFlags(&evStart, cudaEventDisableTiming);
        cudaEventCreateWithFlags(&evX, cudaEventDisableTiming);
        cudaEventCreateWithFlags(&evW, cudaEventDisableTiming);
        cudaEventCreateWithFlags(&evBeta, cudaEventDisableTiming);
        cudaEventCreateWithFlags(&evK, cudaEventDisableTiming);
        cudaEventCreateWithFlags(&evV, cudaEventDisableTiming);
        cudaEventCreateWithFlags(&evConv, cudaEventDisableTiming);
        cudaEventCreateWithFlags(&evFir, cudaEventDisableTiming);
        cudaEventCreateWithFlags(&evScan, cudaEventDisableTiming);
        cudaEventCreateWithFlags(&evS1, cudaEventDisableTiming);
        cudaEventCreateWithFlags(&evStats, cudaEventDisableTiming);
    }

    // fork point
    cudaEventRecord(evStart, 0);

    // stream 0: x->fp16 (critical path head)
    tohalf_kernel<<<8192, 256>>>(x, xh, BLr * HIDv);
    cudaEventRecord(evX, 0);

    // s1: weight prep + hid1 gemm + ssum
    cudaStreamWaitEvent(s1, evStart, 0);
    split_transpose4_kernel<<<dim3(32, 32, 4), 256, 0, s1>>>(Wq, Wk, Wv, Wo,
        Wqh, Wkh, Wvh, Woh, Wql, Wkl, Wvl, Wol);
    cudaEventRecord(evW, s1);
    split_transpose_kernel<<<dim3(16, 32), 256, 0, s1>>>(gW1, g1ah, g1al, 1024, 512);
    cudaStreamWaitEvent(s1, evX, 0);
    gemm_fp16x2<<<dim3(4, 16), 256, GEMM_SMEM, s1>>>(xh, g1ah, g1al, p_hid1, 2048, 512, 1024);
    split_transpose_kernel<<<dim3(16, 32), 256, 0, s1>>>(gW1 + (size_t)4096 * 512, g1bh, g1bl, 1024, 512);
    ssum_kernel<<<24, 256, 0, s1>>>(gW1);
    cudaEventRecord(evS1, s1);

    // s2: beta, then K projection
    cudaStreamWaitEvent(s2, evStart, 0);
    beta_kernel<<<256, 256, 0, s2>>>(x, Wb);
    cudaEventRecord(evBeta, s2);
    cudaStreamWaitEvent(s2, evX, 0);
    cudaStreamWaitEvent(s2, evW, 0);
    gemm_fp16x2<<<dim3(8, 16), 256, GEMM_SMEM, s2>>>(xh, Wkh, Wkl, p_klin, 2048, 1024, 1024);
    cudaEventRecord(evK, s2);

    // s3: V projection
    cudaStreamWaitEvent(s3, evStart, 0);
    cudaStreamWaitEvent(s3, evX, 0);
    cudaStreamWaitEvent(s3, evW, 0);
    gemm_fp16x2<<<dim3(8, 16), 256, GEMM_SMEM, s3>>>(xh, Wvh, Wvl, p_vlin, 2048, 1024, 1024);
    cudaEventRecord(evV, s3);

    // stream 0: Q projection, then conv (needs all three lins)
    cudaStreamWaitEvent(0, evW, 0);
    gemm_fp16x2<<<dim3(8, 16), 256, GEMM_SMEM>>>(xh, Wqh, Wql, p_qlin, 2048, 1024, 1024);
    cudaStreamWaitEvent(0, evK, 0);
    cudaStreamWaitEvent(0, evV, 0);
    conv3_kernel<<<24576, 256>>>(p_qlin, qc, p_q, p_klin, kc, p_k, p_vlin, vc, p_v);
    cudaEventRecord(evConv, 0);

    // s3: FIR branches (needs v only)
    cudaStreamWaitEvent(s3, evConv, 0);
    fir_both_kernel<<<8192, 256, 0, s3>>>(p_v, firs, firl);
    cudaEventRecord(evFir, s3);

    // stream 0: delta path
    cudaStreamWaitEvent(0, evBeta, 0);
    delta_pre_kernel<<<256, 256, PRE_SMEM>>>();
    scan_kernel<<<128, 256, SCAN_SMEM>>>();
    cudaEventRecord(evScan, 0);

    // s2: stats (needs scan + fir), concurrent with tohalf(P)+bpart head
    cudaStreamWaitEvent(s2, evScan, 0);
    cudaStreamWaitEvent(s2, evFir, 0);
    stats_kernel<<<4096, 256, 0, s2>>>();
    cudaEventRecord(evStats, s2);

    // stream 0: P->fp16, bpart gemm, gate, output
    cudaStreamWaitEvent(0, evFir, 0);
    tohalf_kernel<<<32768, 256>>>(p_P, Ph, BLr * NHh * 4 * DKk);
    cudaStreamWaitEvent(0, evS1, 0);
    gemm_fp16x2<<<dim3(4, 64), 256, GEMM_SMEM>>>(Ph, g1bh, g1bl, p_bpart, 8192, 512, 1024);
    cudaStreamWaitEvent(0, evStats, 0);
    gate_final_kernel<<<8192, 256>>>(gb1, gW2, gb2, temp, epsf, onw);
    tohalf_kernel<<<8192, 256>>>(p_omix, oh, BLr * HIDv);
    gemm_fp16x2<<<dim3(8, 16), 256, GEMM_SMEM>>>(oh, Woh, Wol, (float*)d_out, 2048, 1024, 1024);
}

// round 10
// speedup vs baseline: 1.1732x; 1.1732x over previous
#include <cuda_runtime.h>
#include <cuda_fp16.h>
#include <stdint.h>
#include <math.h>

// ---------------- problem constants ----------------
#define Bb   2
#define Ll   1024
#define HIDv 1024
#define NHh  4
#define DKk  256
#define NCc  32
#define CHh  32
#define BLr  2048
#define GHh  512

extern __shared__ char dynsm[];

// ---------------- scratch ----------------
__device__ float g_qkvlin[BLr * 3 * HIDv];   // fused q|k|v projections
__device__ float g_q[BLr * HIDv];
__device__ float g_k[BLr * HIDv];
__device__ float g_v[BLr * HIDv];
__device__ float g_beta[BLr * NHh];
__device__ float g_qn[BLr * HIDv];
__device__ float g_kn[BLr * HIDv];
__device__ float g_u[BLr * HIDv];
__device__ float g_w[BLr * HIDv];
__device__ float g_attn[Bb * NHh * NCc * CHh * CHh];
__device__ float g_P[BLr * NHh * 4 * DKk];
__device__ float g_stats[BLr * NHh * 12];
__device__ float g_ssum[12 * GHh];
__device__ float g_hid1[BLr * GHh];
__device__ float g_bpart[BLr * NHh * GHh];
__device__ float g_omix[BLr * HIDv];

__device__ __half g_xh[BLr * HIDv];
__device__ __half g_Ph[BLr * NHh * 4 * DKk];
__device__ __half g_oh[BLr * HIDv];
__device__ __half g_Wqkvh[3 * HIDv * HIDv], g_Wqkvl[3 * HIDv * HIDv];  // [3072][1024]
__device__ __half g_Woh[HIDv * HIDv], g_Wol[HIDv * HIDv];
__device__ __half g_g1ah[GHh * HIDv], g_g1al[GHh * HIDv];
__device__ __half g_g1bh[GHh * HIDv], g_g1bl[GHh * HIDv];

// ---------------- PTX helpers ----------------
__device__ __forceinline__ uint32_t smem_u32(const void* p) {
    uint32_t a;
    asm("{ .reg .u64 t; cvta.to.shared.u64 t, %1; cvt.u32.u64 %0, t; }" : "=r"(a) : "l"(p));
    return a;
}
__device__ __forceinline__ void ldsm_x4(uint32_t* r, uint32_t addr) {
    asm volatile("ldmatrix.sync.aligned.m8n8.x4.shared.b16 {%0,%1,%2,%3}, [%4];"
                 : "=r"(r[0]), "=r"(r[1]), "=r"(r[2]), "=r"(r[3]) : "r"(addr));
}
__device__ __forceinline__ void mma16816h(float* d, const uint32_t* a, const uint32_t* b) {
    asm volatile(
        "mma.sync.aligned.m16n8k16.row.col.f32.f16.f16.f32 "
        "{%0,%1,%2,%3}, {%4,%5,%6,%7}, {%8,%9}, {%0,%1,%2,%3};"
        : "+f"(d[0]), "+f"(d[1]), "+f"(d[2]), "+f"(d[3])
        : "r"(a[0]), "r"(a[1]), "r"(a[2]), "r"(a[3]), "r"(b[0]), "r"(b[1]));
}

// ---------------- fp16x2 HMMA GEMM: C[M,N] = A[M,K] @ Bt[N,K]^T ----------------
// 512 threads, 16 warps (4m x 4n), warp tile 32x32, k-chunk 32, double buffer.
#define LDAh 40
#define TILEB (128 * LDAh * 2)        // 10240 B per operand tile
#define GEMM_SMEM (2 * 3 * TILEB)     // 61440 B

__global__ __launch_bounds__(512, 1) void gemm_fp16x2(
    const __half* __restrict__ A,
    const __half* __restrict__ Bh, const __half* __restrict__ Bl,
    float* __restrict__ C, int M, int N, int K) {
    char* smc = dynsm;
    uint32_t sbase = smem_u32(smc);
    int t = threadIdx.x;
    int lane = t & 31;
    int wid = t >> 5;          // 0..15
    int wm = wid & 3;          // 4 m-groups of 32 rows
    int wn = wid >> 2;         // 4 n-groups of 32 cols
    int m0 = blockIdx.y * 128;
    int n0 = blockIdx.x * 128;

    float acc[2][4][4];
#pragma unroll
    for (int i = 0; i < 2; i++)
#pragma unroll
        for (int j = 0; j < 4; j++)
#pragma unroll
            for (int c = 0; c < 4; c++) acc[i][j][c] = 0.f;

    uint4 rg[3];
    int ldrow = t >> 2;        // 0..127
    int ldq = t & 3;
    int soff = (ldrow * LDAh + ldq * 8) * 2;

    int a_off = ((wm * 32 + (lane & 15)) * LDAh + ((lane >> 4) << 3)) * 2;
    int b_off = ((wn * 32 + (lane & 7) + ((lane >> 4) << 3)) * LDAh + (((lane >> 3) & 1) << 3)) * 2;

    const int S = K / 32;

    {
        size_t ga = (size_t)(m0 + ldrow) * K + ldq * 8;
        size_t gb = (size_t)(n0 + ldrow) * K + ldq * 8;
        rg[0] = *(const uint4*)(A + ga);
        rg[1] = *(const uint4*)(Bh + gb);
        rg[2] = *(const uint4*)(Bl + gb);
    }
    *(uint4*)(smc + soff)             = rg[0];
    *(uint4*)(smc + TILEB + soff)     = rg[1];
    *(uint4*)(smc + 2 * TILEB + soff) = rg[2];
    __syncthreads();

    for (int s = 0; s < S; s++) {
        int cur = s & 1;
        if (s + 1 < S) {
            int k0 = (s + 1) * 32;
            size_t ga = (size_t)(m0 + ldrow) * K + k0 + ldq * 8;
            size_t gb = (size_t)(n0 + ldrow) * K + k0 + ldq * 8;
            rg[0] = *(const uint4*)(A + ga);
            rg[1] = *(const uint4*)(Bh + gb);
            rg[2] = *(const uint4*)(Bl + gb);
        }

        uint32_t sb = sbase + cur * 3 * TILEB;
#pragma unroll
        for (int kk = 0; kk < 32; kk += 16) {
            uint32_t ah[2][4], bhf[2][4], blf[2][4];
#pragma unroll
            for (int mi = 0; mi < 2; mi++)
                ldsm_x4(ah[mi], sb + a_off + mi * 16 * LDAh * 2 + kk * 2);
#pragma unroll
            for (int nb = 0; nb < 2; nb++)
                ldsm_x4(bhf[nb], sb + TILEB + b_off + nb * 16 * LDAh * 2 + kk * 2);
#pragma unroll
            for (int nb = 0; nb < 2; nb++)
                ldsm_x4(blf[nb], sb + 2 * TILEB + b_off + nb * 16 * LDAh * 2 + kk * 2);
#pragma unroll
            for (int mi = 0; mi < 2; mi++)
#pragma unroll
                for (int nb = 0; nb < 2; nb++) {
                    mma16816h(acc[mi][nb * 2 + 0], ah[mi], &bhf[nb][0]);
                    mma16816h(acc[mi][nb * 2 + 1], ah[mi], &bhf[nb][2]);
                }
#pragma unroll
            for (int mi = 0; mi < 2; mi++)
#pragma unroll
                for (int nb = 0; nb < 2; nb++) {
                    mma16816h(acc[mi][nb * 2 + 0], ah[mi], &blf[nb][0]);
                    mma16816h(acc[mi][nb * 2 + 1], ah[mi], &blf[nb][2]);
                }
        }

        if (s + 1 < S) {
            char* bb = smc + ((s + 1) & 1) * 3 * TILEB;
            *(uint4*)(bb + soff)             = rg[0];
            *(uint4*)(bb + TILEB + soff)     = rg[1];
            *(uint4*)(bb + 2 * TILEB + soff) = rg[2];
        }
        __syncthreads();
    }

    int frow = lane >> 2;
    int fcol = (lane & 3) * 2;
#pragma unroll
    for (int mi = 0; mi < 2; mi++) {
#pragma unroll
        for (int ni = 0; ni < 4; ni++) {
            int row = m0 + wm * 32 + mi * 16 + frow;
            int col = n0 + wn * 32 + ni * 8 + fcol;
            *(float2*)(C + (size_t)row * N + col) = make_float2(acc[mi][ni][0], acc[mi][ni][1]);
            *(float2*)(C + (size_t)(row + 8) * N + col) = make_float2(acc[mi][ni][2], acc[mi][ni][3]);
        }
    }
}

// ---------------- fp32 -> fp16 convert ----------------
__global__ void tohalf_kernel(const float* __restrict__ src,
                              __half* __restrict__ dst, int n) {
    int i = blockIdx.x * 256 + threadIdx.x;
    if (i < n) dst[i] = __float2half(src[i]);
}

// src [K][N] fp32 -> dst [N][K] fp16 (hi/lo)
__global__ void split_transpose_kernel(const float* __restrict__ src,
                                       __half* __restrict__ hi,
                                       __half* __restrict__ lo,
                                       int K, int N) {
    __shared__ float tile[32][33];
    int k0 = blockIdx.y * 32;
    int n0 = blockIdx.x * 32;
    int tx = threadIdx.x & 31;
    int ty = threadIdx.x >> 5;
    for (int r = ty; r < 32; r += 8) tile[r][tx] = src[(size_t)(k0 + r) * N + n0 + tx];
    __syncthreads();
    for (int r = ty; r < 32; r += 8) {
        float v = tile[tx][r];
        __half h = __float2half(v);
        size_t o = (size_t)(n0 + r) * K + k0 + tx;
        hi[o] = h;
        lo[o] = __float2half(v - __half2float(h));
    }
}

// 4 fused 1024x1024 weight split-transposes (base pointers select destination)
__global__ void split_transpose4_kernel(const float* __restrict__ s0, const float* __restrict__ s1,
                                        const float* __restrict__ s2, const float* __restrict__ s3,
                                        __half* __restrict__ h0, __half* __restrict__ h1,
                                        __half* __restrict__ h2, __half* __restrict__ h3,
                                        __half* __restrict__ l0, __half* __restrict__ l1,
                                        __half* __restrict__ l2, __half* __restrict__ l3) {
    __shared__ float tile[32][33];
    int z = blockIdx.z;
    const float* src = (z == 0) ? s0 : (z == 1) ? s1 : (z == 2) ? s2 : s3;
    __half* hi = (z == 0) ? h0 : (z == 1) ? h1 : (z == 2) ? h2 : h3;
    __half* lo = (z == 0) ? l0 : (z == 1) ? l1 : (z == 2) ? l2 : l3;
    int k0 = blockIdx.y * 32;
    int n0 = blockIdx.x * 32;
    int tx = threadIdx.x & 31;
    int ty = threadIdx.x >> 5;
    for (int r = ty; r < 32; r += 8) tile[r][tx] = src[(size_t)(k0 + r) * 1024 + n0 + tx];
    __syncthreads();
    for (int r = ty; r < 32; r += 8) {
        float v = tile[tx][r];
        __half h = __float2half(v);
        size_t o = (size_t)(n0 + r) * 1024 + k0 + tx;
        hi[o] = h;
        lo[o] = __float2half(v - __half2float(h));
    }
}

// ---------------- beta = sigmoid(x @ Wb) ----------------
__global__ void beta_kernel(const float* __restrict__ x, const float* __restrict__ Wb) {
    int gw   = (blockIdx.x << 3) + (threadIdx.x >> 5);
    int lane = threadIdx.x & 31;
    const float* xr = x + (size_t)gw * HIDv;
    float a0 = 0.f, a1 = 0.f, a2 = 0.f, a3 = 0.f;
    for (int r = lane; r < HIDv; r += 32) {
        float xv = xr[r];
        const float* wb = Wb + r * 4;
        a0 += xv * wb[0]; a1 += xv * wb[1]; a2 += xv * wb[2]; a3 += xv * wb[3];
    }
    for (int o = 16; o; o >>= 1) {
        a0 += __shfl_xor_sync(0xffffffffu, a0, o);
        a1 += __shfl_xor_sync(0xffffffffu, a1, o);
        a2 += __shfl_xor_sync(0xffffffffu, a2, o);
        a3 += __shfl_xor_sync(0xffffffffu, a3, o);
    }
    if (!lane) {
        float* bp = &g_beta[gw * 4];
        bp[0] = 1.f / (1.f + expf(-a0));
        bp[1] = 1.f / (1.f + expf(-a1));
        bp[2] = 1.f / (1.f + expf(-a2));
        bp[3] = 1.f / (1.f + expf(-a3));
    }
}

// ---------------- fused: 3x causal depthwise conv (k=4) + silu (reads fused qkvlin) ----------------
__global__ void conv3_kernel(const float* __restrict__ qkvlin,
                             const float* __restrict__ w0, float* __restrict__ out0,
                             const float* __restrict__ w1, float* __restrict__ out1,
                             const float* __restrict__ w2, float* __restrict__ out2) {
    int which = blockIdx.x >> 13;
    int bx = blockIdx.x & 8191;
    const float* w = which == 0 ? w0 : (which == 1 ? w1 : w2);
    float* out     = which == 0 ? out0 : (which == 1 ? out1 : out2);
    int idx = bx * 256 + threadIdx.x;
    int c = idx & 1023;
    int l = (idx >> 10) & 1023;
    int b = idx >> 20;
    const float* wc = w + c * 4;
    float acc = 0.f;
#pragma unroll
    for (int j = 0; j < 4; j++) {
        int ls = l - 3 + j;
        if (ls >= 0) acc += qkvlin[((size_t)b * Ll + ls) * 3072 + which * 1024 + c] * wc[j];
    }
    out[idx] = acc / (1.f + expf(-acc));
}

// ---------------- fused FIR: short (K=3), long (K=31), v copy ----------------
__global__ void fir_both_kernel(const float* __restrict__ v,
                                const float* __restrict__ fs,
                                const float* __restrict__ fl) {
    int idx = blockIdx.x * 256 + threadIdx.x;
    int d = idx & 255;
    int h = (idx >> 8) & 3;
    int l = (idx >> 10) & 1023;
    int b = idx >> 20;
    const float* fls = fl + (h * 256 + d) * 31;
    const float* fss = fs + (h * 256 + d) * 3;
    float accL = 0.f, accS = 0.f, vcur = 0.f;
    for (int j = 0; j < 31; j++) {
        int ls = l - 30 + j;
        if (ls >= 0) {
            float vv = v[(((size_t)b * Ll + ls) * NHh + h) * 256 + d];
            accL += vv * fls[j];
            if (j >= 28) accS += vv * fss[j - 28];
            if (j == 30) vcur = vv;
        }
    }
    size_t row = ((size_t)b * Ll + l) * NHh + h;
    g_P[(row * 4 + 0) * 256 + d] = accS;
    g_P[(row * 4 + 1) * 256 + d] = accL;
    g_P[(row * 4 + 3) * 256 + d] = vcur;
}

// ---------------- delta pre ----------------
__global__ void delta_pre_kernel() {
    float* smf = (float*)dynsm;
    float* qs  = smf;
    float* kn  = qs + 8224;
    float* vb  = kn + 8224;
    float* Am  = vb + 8224;
    float* Tm  = Am + 1024;
    float* bet = Tm + 1056;
    float* rsq = bet + 32;
    float* rsk = rsq + 32;

    int t  = threadIdx.x;
    int n  = blockIdx.x & 31;
    int bh = blockIdx.x >> 5;
    int h  = bh & 3;
    int b  = bh >> 2;
    int l0 = n * CHh;
    size_t gbase = (((size_t)b * Ll + l0) * NHh + h) * 256;
    size_t obase = ((((size_t)b * NHh + h) * NCc + n) * CHh) * 256;

    for (int idx = t; idx < CHh * 256; idx += 256) {
        int c = idx >> 8;
        int d = idx & 255;
        size_t off = gbase + (size_t)c * (NHh * 256) + d;
        qs[c * 257 + d] = g_q[off];
        kn[c * 257 + d] = g_k[off];
        vb[c * 257 + d] = g_v[off];
    }
    if (t < CHh) bet[t] = g_beta[((size_t)b * Ll + l0 + t) * NHh + h];
    __syncthreads();

    int lane = t & 31;
    int wid = t >> 5;
    for (int r = wid; r < CHh; r += 8) {
        float sq = 0.f, sk = 0.f;
        for (int d = lane; d < 256; d += 32) {
            float a = qs[r * 257 + d]; sq += a * a;
            float c2 = kn[r * 257 + d]; sk += c2 * c2;
        }
        for (int o = 16; o; o >>= 1) {
            sq += __shfl_xor_sync(0xffffffffu, sq, o);
            sk += __shfl_xor_sync(0xffffffffu, sk, o);
        }
        if (!lane) { rsq[r] = rsqrtf(sq + 1e-6f); rsk[r] = rsqrtf(sk + 1e-6f); }
    }
    __syncthreads();

    for (int idx = t; idx < CHh * 256; idx += 256) {
        int c = idx >> 8;
        int d = idx & 255;
        float qv = qs[c * 257 + d] * rsq[c]; qs[c * 257 + d] = qv; g_qn[obase + idx] = qv;
        float kv = kn[c * 257 + d] * rsk[c]; kn[c * 257 + d] = kv; g_kn[obase + idx] = kv;
        vb[c * 257 + d] *= bet[c];
    }
    __syncthreads();

    size_t abase = ((((size_t)b * NHh + h) * NCc + n) << 10);
    for (int p = t; p < 1024; p += 256) {
        int i = p >> 5;
        int jj = p & 31;
        float dq = 0.f, dk2 = 0.f;
        if (jj <= i) {
            const float* qi = &qs[i * 257];
            const float* kj = &kn[jj * 257];
            for (int d = 0; d < 256; d++) dq += qi[d] * kj[d];
        }
        if (jj < i) {
            const float* ki = &kn[i * 257];
            const float* kj = &kn[jj * 257];
            for (int d = 0; d < 256; d++) dk2 += ki[d] * kj[d];
        }
        Am[p] = (jj < i) ? (-bet[i] * dk2) : 0.f;
        g_attn[abase + p] = (jj <= i) ? dq : 0.f;
    }
    __syncthreads();

    if (t < 32) {
        Tm[t] = (t == 0) ? 1.f : 0.f;
        for (int i = 1; i < 32; i++) {
            float acc = (i == t) ? 1.f : 0.f;
            for (int m = 0; m < i; m++) acc += Am[i * 32 + m] * Tm[m * 33 + t];
            Tm[i * 33 + t] = acc;
        }
    }
    __syncthreads();

    {
        int d = t;
        for (int r = 0; r < 32; r++) {
            float au = 0.f, aw = 0.f;
            const float* Tr = &Tm[r * 33];
            for (int m = 0; m <= r; m++) {
                float tv = Tr[m];
                au += tv * vb[m * 257 + d];
                aw += tv * bet[m] * kn[m * 257 + d];
            }
            g_u[obase + r * 256 + d] = au;
            g_w[obase + r * 256 + d] = aw;
        }
    }
}

// ---------------- serial chunk scan ----------------
#define KST 272
__global__ void scan_kernel() {
    float* smf = (float*)dynsm;
    float* S  = smf;
    float* qn = S + 4352;
    float* kn = qn + 8704;
    float* wS = kn + 8704;
    float* un = wS + 8704;
    float* uu = un + 544;
    float* at = uu + 512;

    int t = threadIdx.x;
    int s_idx = blockIdx.x & 15;
    int bh = blockIdx.x >> 4;
    int h = bh & 3;
    int b = bh >> 2;
    int j0 = s_idx * 16;

    for (int i = t; i < 4352; i += 256) S[i] = 0.f;
    __syncthreads();

    int j = t & 15;
    int cg = t >> 4;
    int c0 = cg * 2;
    int c1 = c0 + 1;

    for (int n = 0; n < NCc; n++) {
        size_t base = ((((size_t)b * NHh + h) * NCc + n) * CHh) * 256;
        for (int idx = t; idx < 32 * 64; idx += 256) {
            int c = idx >> 6;
            int dq = (idx & 63) << 2;
            *(float4*)(&qn[c * KST + dq]) = *(const float4*)(&g_qn[base + c * 256 + dq]);
            *(float4*)(&kn[c * KST + dq]) = *(const float4*)(&g_kn[base + c * 256 + dq]);
            *(float4*)(&wS[c * KST + dq]) = *(const float4*)(&g_w [base + c * 256 + dq]);
        }
        for (int idx = t; idx < 512; idx += 256) {
            int c = idx >> 4;
            int jj = idx & 15;
            uu[idx] = g_u[base + c * 256 + j0 + jj];
        }
        size_t abase = ((((size_t)b * NHh + h) * NCc + n) << 10);
        for (int idx = t; idx < 1024; idx += 256) {
            int c = idx >> 5;
            int cp = idx & 31;
            at[c * 33 + cp] = g_attn[abase + idx];
        }
        __syncthreads();

        float a0 = uu[c0 * 16 + j];
        float a1 = uu[c1 * 16 + j];
        float o0 = 0.f, o1 = 0.f;
        const float* w0 = &wS[c0 * KST];
        const float* w1 = &wS[c1 * KST];
        const float* q0 = &qn[c0 * KST];
        const float* q1 = &qn[c1 * KST];
#pragma unroll 8
        for (int d4 = 0; d4 < 64; d4++) {
            int d = d4 << 2;
            float4 wv0 = *(const float4*)(&w0[d]);
            float4 wv1 = *(const float4*)(&w1[d]);
            float4 qv0 = *(const float4*)(&q0[d]);
            float4 qv1 = *(const float4*)(&q1[d]);
            float s0 = S[(d + 0) * 17 + j];
            float s1 = S[(d + 1) * 17 + j];
            float s2 = S[(d + 2) * 17 + j];
            float s3 = S[(d + 3) * 17 + j];
            a0 -= wv0.x * s0 + wv0.y * s1 + wv0.z * s2 + wv0.w * s3;
            a1 -= wv1.x * s0 + wv1.y * s1 + wv1.z * s2 + wv1.w * s3;
            o0 += qv0.x * s0 + qv0.y * s1 + qv0.z * s2 + qv0.w * s3;
            o1 += qv1.x * s0 + qv1.y * s1 + qv1.z * s2 + qv1.w * s3;
        }
        un[c0 * 17 + j] = a0;
        un[c1 * 17 + j] = a1;
        __syncthreads();

        for (int cp = 0; cp <= c0; cp++) o0 += at[c0 * 33 + cp] * un[cp * 17 + j];
        for (int cp = 0; cp <= c1; cp++) o1 += at[c1 * 33 + cp] * un[cp * 17 + j];
        {
            int l = n * CHh;
            size_t r0 = (((size_t)b * Ll + l + c0) * NHh + h) * 4 + 2;
            size_t r1 = (((size_t)b * Ll + l + c1) * NHh + h) * 4 + 2;
            g_P[r0 * 256 + j0 + j] = o0;
            g_P[r1 * 256 + j0 + j] = o1;
        }

#pragma unroll
        for (int blk = 0; blk < 4; blk++) {
            int d0 = cg * 16 + blk * 4;
            float s0 = S[(d0 + 0) * 17 + j];
            float s1 = S[(d0 + 1) * 17 + j];
            float s2 = S[(d0 + 2) * 17 + j];
            float s3 = S[(d0 + 3) * 17 + j];
            for (int c = 0; c < 32; c++) {
                float u = un[c * 17 + j];
                float4 kv = *(const float4*)(&kn[c * KST + d0]);
                s0 += kv.x * u; s1 += kv.y * u; s2 += kv.z * u; s3 += kv.w * u;
            }
            S[(d0 + 0) * 17 + j] = s0;
            S[(d0 + 1) * 17 + j] = s1;
            S[(d0 + 2) * 17 + j] = s2;
            S[(d0 + 3) * 17 + j] = s3;
        }
        __syncthreads();
    }
}

// ---------------- per-branch stats ----------------
__global__ void stats_kernel() {
    int gw = (blockIdx.x << 3) + (threadIdx.x >> 5);
    int lane = threadIdx.x & 31;
    int row = gw >> 2;
    int jb = gw & 3;
    const float* p = &g_P[((size_t)row * 4 + jb) << 8];
    float smv = 0.f, sq = 0.f, mx = -3.4e38f;
    for (int d = lane; d < 256; d += 32) {
        float v = p[d];
        smv += v; sq += v * v; mx = fmaxf(mx, v);
    }
    for (int o = 16; o; o >>= 1) {
        smv += __shfl_xor_sync(0xffffffffu, smv, o);
        sq  += __shfl_xor_sync(0xffffffffu, sq, o);
        mx   = fmaxf(mx, __shfl_xor_sync(0xffffffffu, mx, o));
    }
    if (!lane) {
        float* s = &g_stats[(size_t)row * 12 + jb * 3];
        s[0] = smv * (1.f / 256.f);
        s[1] = sqrtf(fmaxf(sq * (1.f / 256.f), 1e-8f));
        s[2] = mx;
    }
}

// ---------------- gW1 stat-block column sums ----------------
__global__ void ssum_kernel(const float* __restrict__ gW1) {
    int idx = blockIdx.x * 256 + threadIdx.x;
    int s12 = idx / GHh;
    int nn = idx % GHh;
    float a = 0.f;
    const float* base = gW1 + (size_t)(1024 + s12 * 256) * GHh + nn;
    for (int r = 0; r < 256; r++) a += base[(size_t)r * GHh];
    g_ssum[idx] = a;
}

// ---------------- gate finalize ----------------
__global__ void gate_final_kernel(const float* __restrict__ gb1,
                                  const float* __restrict__ gW2,
                                  const float* __restrict__ gb2,
                                  const float* __restrict__ temp,
                                  const float* __restrict__ epsf,
                                  const float* __restrict__ onw) {
    __shared__ float mid[GHh];
    __shared__ float st[12];
    __shared__ float w4[4];
    __shared__ float red[256];
    int row = blockIdx.x;
    int t = threadIdx.x;
    int h = row & 3;
    int bl = row >> 2;

    if (t < 12) st[t] = g_stats[(size_t)row * 12 + t];
    __syncthreads();

    for (int nn = t; nn < GHh; nn += 256) {
        float val = g_hid1[(size_t)bl * GHh + nn] + g_bpart[(size_t)row * GHh + nn] + gb1[nn];
#pragma unroll
        for (int s12 = 0; s12 < 12; s12++) val += st[s12] * g_ssum[s12 * GHh + nn];
        mid[nn] = 0.5f * val * (1.f + erff(val * 0.70710678118654752f));
    }
    __syncthreads();

    {
        int o = t & 3;
        float p = 0.f;
        for (int nidx = t >> 2; nidx < GHh; nidx += 64) p += mid[nidx] * gW2[nidx * 4 + o];
        red[t] = p;
    }
    __syncthreads();
    if (t < 4) {
        float lg = gb2[t];
        for (int g = 0; g < 64; g++) lg += red[g * 4 + t];
        red[t] = lg;
    }
    __syncthreads();
    if (t == 0) {
        float tc = fminf(fmaxf(temp[h], 0.2f), 10.f);
        float l0 = red[0] / tc, l1 = red[1] / tc, l2 = red[2] / tc, l3 = red[3] / tc;
        float mx = fmaxf(fmaxf(l0, l1), fmaxf(l2, l3));
        float e0 = expf(l0 - mx), e1 = expf(l1 - mx), e2 = expf(l2 - mx), e3 = expf(l3 - mx);
        float s = e0 + e1 + e2 + e3;
        float w0 = e0 / s, w1 = e1 / s, w2 = e2 / s, w3 = e3 / s;
        float f0 = fminf(fmaxf(epsf[h * 4 + 0], 1e-7f), 0.1f);
        float f1 = fminf(fmaxf(epsf[h * 4 + 1], 1e-7f), 0.1f);
        float f2 = fminf(fmaxf(epsf[h * 4 + 2], 1e-7f), 0.1f);
        float f3 = fminf(fmaxf(epsf[h * 4 + 3], 1e-7f), 0.1f);
        w0 = fmaxf(w0, f0); w1 = fmaxf(w1, f1); w2 = fmaxf(w2, f2); w3 = fmaxf(w3, f3);
        float s2 = w0 + w1 + w2 + w3;
        w4[0] = w0 / s2; w4[1] = w1 / s2; w4[2] = w2 / s2; w4[3] = w3 / s2;
    }
    __syncthreads();

    float od = 0.f;
#pragma unroll
    for (int jj = 0; jj < 4; jj++) od += w4[jj] * g_P[((size_t)row * 4 + jj) * 256 + t];
    red[t] = od * od;
    __syncthreads();
    for (int s = 128; s > 0; s >>= 1) {
        if (t < s) red[t] += red[t + s];
        __syncthreads();
    }
    float ms = red[0] * (1.f / 256.f);
    g_omix[(size_t)bl * HIDv + h * 256 + t] = od * rsqrtf(ms + 1e-5f) * onw[t];
}

// ---------------- host launcher ----------------
static const int PRE_SMEM  = 26848 * 4;
static const int SCAN_SMEM = 32576 * 4;

extern "C" void kernel_launch(void* const* d_in, const int* in_sizes, int n_in,
                              void* d_out, int out_size) {
    const float *x = 0, *Wq = 0, *Wk = 0, *Wv = 0, *Wb = 0, *qc = 0, *kc = 0, *vc = 0;
    const float *firs = 0, *firl = 0, *gW1 = 0, *gb1 = 0, *gW2 = 0, *gb2 = 0;
    const float *temp = 0, *epsf = 0, *onw = 0, *Wo = 0;
    int occ1M = 0, occ4k = 0, occ4 = 0;
    for (int i = 0; i < n_in; i++) {
        const float* p = (const float*)d_in[i];
        switch (in_sizes[i]) {
            case 2097152: x = p; break;
            case 1048576:
                if (occ1M == 0) Wq = p; else if (occ1M == 1) Wk = p;
                else if (occ1M == 2) Wv = p; else Wo = p;
                occ1M++; break;
            case 4096:
                if (occ4k == 0) Wb = p; else if (occ4k == 1) qc = p;
                else if (occ4k == 2) kc = p; else vc = p;
                occ4k++; break;
            case 2621440: gW1 = p; break;
            case 512:     gb1 = p; break;
            case 2048:    gW2 = p; break;
            case 4:       if (occ4 == 0) gb2 = p; else temp = p; occ4++; break;
            case 16:      epsf = p; break;
            case 256:     onw = p; break;
            case 3072:    firs = p; break;
            case 31744:   firl = p; break;
            default: break;
        }
    }

    float *p_qkvlin, *p_q, *p_k, *p_v, *p_P, *p_hid1, *p_bpart, *p_omix;
    cudaGetSymbolAddress((void**)&p_qkvlin, g_qkvlin);
    cudaGetSymbolAddress((void**)&p_q, g_q);
    cudaGetSymbolAddress((void**)&p_k, g_k);
    cudaGetSymbolAddress((void**)&p_v, g_v);
    cudaGetSymbolAddress((void**)&p_P, g_P);
    cudaGetSymbolAddress((void**)&p_hid1, g_hid1);
    cudaGetSymbolAddress((void**)&p_bpart, g_bpart);
    cudaGetSymbolAddress((void**)&p_omix, g_omix);

    __half *xh, *Ph, *oh;
    __half *Wqkvh, *Wqkvl, *Woh, *Wol, *g1ah, *g1al, *g1bh, *g1bl;
    cudaGetSymbolAddress((void**)&xh, g_xh);
    cudaGetSymbolAddress((void**)&Ph, g_Ph);
    cudaGetSymbolAddress((void**)&oh, g_oh);
    cudaGetSymbolAddress((void**)&Wqkvh, g_Wqkvh); cudaGetSymbolAddress((void**)&Wqkvl, g_Wqkvl);
    cudaGetSymbolAddress((void**)&Woh, g_Woh);     cudaGetSymbolAddress((void**)&Wol, g_Wol);
    cudaGetSymbolAddress((void**)&g1ah, g_g1ah);   cudaGetSymbolAddress((void**)&g1al, g_g1al);
    cudaGetSymbolAddress((void**)&g1bh, g_g1bh);   cudaGetSymbolAddress((void**)&g1bl, g_g1bl);

    cudaFuncSetAttribute(delta_pre_kernel, cudaFuncAttributeMaxDynamicSharedMemorySize, PRE_SMEM);
    cudaFuncSetAttribute(scan_kernel, cudaFuncAttributeMaxDynamicSharedMemorySize, SCAN_SMEM);
    cudaFuncSetAttribute(gemm_fp16x2, cudaFuncAttributeMaxDynamicSharedMemorySize, GEMM_SMEM);

    const size_t W1M = (size_t)1024 * 1024;

    // single stream; launch #4 = merged QKV GEMM (profiled)
    tohalf_kernel<<<8192, 256>>>(x, xh, BLr * HIDv);                              // 1
    split_transpose4_kernel<<<dim3(32, 32, 4), 256>>>(Wq, Wk, Wv, Wo,
        Wqkvh, Wqkvh + W1M, Wqkvh + 2 * W1M, Woh,
        Wqkvl, Wqkvl + W1M, Wqkvl + 2 * W1M, Wol);                                // 2
    split_transpose_kernel<<<dim3(16, 32), 256>>>(gW1, g1ah, g1al, 1024, 512);    // 3
    gemm_fp16x2<<<dim3(24, 16), 512, GEMM_SMEM>>>(xh, Wqkvh, Wqkvl, p_qkvlin, 2048, 3072, 1024);  // 4 <- profiled
    split_transpose_kernel<<<dim3(16, 32), 256>>>(gW1 + (size_t)4096 * 512, g1bh, g1bl, 1024, 512);
    ssum_kernel<<<24, 256>>>(gW1);
    beta_kernel<<<256, 256>>>(x, Wb);
    conv3_kernel<<<24576, 256>>>(p_qkvlin, qc, p_q, kc, p_k, vc, p_v);
    delta_pre_kernel<<<256, 256, PRE_SMEM>>>();
    scan_kernel<<<128, 256, SCAN_SMEM>>>();
    fir_both_kernel<<<8192, 256>>>(p_v, firs, firl);
    stats_kernel<<<4096, 256>>>();
    tohalf_kernel<<<32768, 256>>>(p_P, Ph, BLr * NHh * 4 * DKk);
    gemm_fp16x2<<<dim3(4, 16), 512, GEMM_SMEM>>>(xh, g1ah, g1al, p_hid1, 2048, 512, 1024);
    gemm_fp16x2<<<dim3(4, 64), 512, GEMM_SMEM>>>(Ph, g1bh, g1bl, p_bpart, 8192, 512, 1024);
    gate_final_kernel<<<8192, 256>>>(gb1, gW2, gb2, temp, epsf, onw);
    tohalf_kernel<<<8192, 256>>>(p_omix, oh, BLr * HIDv);
    gemm_fp16x2<<<dim3(8, 16), 512, GEMM_SMEM>>>(oh, Woh, Wol, (float*)d_out, 2048, 1024, 1024);
}

// round 11
// speedup vs baseline: 1.3068x; 1.1139x over previous
#include <cuda_runtime.h>
#include <cuda_fp16.h>
#include <stdint.h>
#include <math.h>

// ---------------- problem constants ----------------
#define Bb   2
#define Ll   1024
#define HIDv 1024
#define NHh  4
#define DKk  256
#define NCc  32
#define CHh  32
#define BLr  2048
#define GHh  512

extern __shared__ char dynsm[];

// ---------------- scratch ----------------
__device__ float g_qkvlin[BLr * 3 * HIDv];
__device__ float g_q[BLr * HIDv];
__device__ float g_k[BLr * HIDv];
__device__ float g_v[BLr * HIDv];
__device__ float g_beta[BLr * NHh];
__device__ float g_qn[BLr * HIDv];
__device__ float g_kn[BLr * HIDv];
__device__ float g_u[BLr * HIDv];
__device__ float g_w[BLr * HIDv];
__device__ float g_attn[Bb * NHh * NCc * CHh * CHh];
__device__ float g_P[BLr * NHh * 4 * DKk];
__device__ float g_ssum[12 * GHh];
__device__ float g_hid1[BLr * GHh];
__device__ float g_bpart[BLr * NHh * GHh];

__device__ __half g_xh[BLr * HIDv];
__device__ __half g_Ph[BLr * NHh * 4 * DKk];
__device__ __half g_oh[BLr * HIDv];
__device__ __half g_Wqkvh[3 * HIDv * HIDv], g_Wqkvl[3 * HIDv * HIDv];
__device__ __half g_Woh[HIDv * HIDv], g_Wol[HIDv * HIDv];
__device__ __half g_g1ah[GHh * HIDv], g_g1al[GHh * HIDv];
__device__ __half g_g1bh[GHh * HIDv], g_g1bl[GHh * HIDv];

// ---------------- PTX helpers ----------------
__device__ __forceinline__ uint32_t smem_u32(const void* p) {
    uint32_t a;
    asm("{ .reg .u64 t; cvta.to.shared.u64 t, %1; cvt.u32.u64 %0, t; }" : "=r"(a) : "l"(p));
    return a;
}
__device__ __forceinline__ void ldsm_x4(uint32_t* r, uint32_t addr) {
    asm volatile("ldmatrix.sync.aligned.m8n8.x4.shared.b16 {%0,%1,%2,%3}, [%4];"
                 : "=r"(r[0]), "=r"(r[1]), "=r"(r[2]), "=r"(r[3]) : "r"(addr));
}
__device__ __forceinline__ void mma16816h(float* d, const uint32_t* a, const uint32_t* b) {
    asm volatile(
        "mma.sync.aligned.m16n8k16.row.col.f32.f16.f16.f32 "
        "{%0,%1,%2,%3}, {%4,%5,%6,%7}, {%8,%9}, {%0,%1,%2,%3};"
        : "+f"(d[0]), "+f"(d[1]), "+f"(d[2]), "+f"(d[3])
        : "r"(a[0]), "r"(a[1]), "r"(a[2]), "r"(a[3]), "r"(b[0]), "r"(b[1]));
}

// ---------------- fp16x2 HMMA GEMM (R8-proven: 256 thr, warp tile 64x32) ----------------
#define LDAh 40
#define TILEB (128 * LDAh * 2)
#define GEMM_SMEM (2 * 3 * TILEB)     // 61440 B

__global__ __launch_bounds__(256, 1) void gemm_fp16x2(
    const __half* __restrict__ A,
    const __half* __restrict__ Bh, const __half* __restrict__ Bl,
    float* __restrict__ C, int M, int N, int K) {
    char* smc = dynsm;
    uint32_t sbase = smem_u32(smc);
    int t = threadIdx.x;
    int lane = t & 31;
    int wid = t >> 5;
    int wm = wid & 1;
    int wn = wid >> 1;
    int m0 = blockIdx.y * 128;
    int n0 = blockIdx.x * 128;

    float acc[4][4][4];
#pragma unroll
    for (int i = 0; i < 4; i++)
#pragma unroll
        for (int j = 0; j < 4; j++)
#pragma unroll
            for (int c = 0; c < 4; c++) acc[i][j][c] = 0.f;

    uint4 rg[6];
    int ldrow = t >> 2;
    int ldq = t & 3;

    int a_off = ((wm * 64 + (lane & 15)) * LDAh + ((lane >> 4) << 3)) * 2;
    int b_off = ((wn * 32 + (lane & 7) + ((lane >> 4) << 3)) * LDAh + (((lane >> 3) & 1) << 3)) * 2;

    const int S = K / 32;

#pragma unroll
    for (int i = 0; i < 2; i++) {
        int row = ldrow + i * 64;
        size_t ga = (size_t)(m0 + row) * K + ldq * 8;
        size_t gb = (size_t)(n0 + row) * K + ldq * 8;
        rg[i]     = *(const uint4*)(A + ga);
        rg[2 + i] = *(const uint4*)(Bh + gb);
        rg[4 + i] = *(const uint4*)(Bl + gb);
    }
#pragma unroll
    for (int i = 0; i < 2; i++) {
        int row = ldrow + i * 64;
        int off = (row * LDAh + ldq * 8) * 2;
        *(uint4*)(smc + off)             = rg[i];
        *(uint4*)(smc + TILEB + off)     = rg[2 + i];
        *(uint4*)(smc + 2 * TILEB + off) = rg[4 + i];
    }
    __syncthreads();

    for (int s = 0; s < S; s++) {
        int cur = s & 1;
        if (s + 1 < S) {
            int k0 = (s + 1) * 32;
#pragma unroll
            for (int i = 0; i < 2; i++) {
                int row = ldrow + i * 64;
                size_t ga = (size_t)(m0 + row) * K + k0 + ldq * 8;
                size_t gb = (size_t)(n0 + row) * K + k0 + ldq * 8;
                rg[i]     = *(const uint4*)(A + ga);
                rg[2 + i] = *(const uint4*)(Bh + gb);
                rg[4 + i] = *(const uint4*)(Bl + gb);
            }
        }

        uint32_t sb = sbase + cur * 3 * TILEB;
#pragma unroll
        for (int kk = 0; kk < 32; kk += 16) {
            uint32_t ah[4][4], bhf[2][4], blf[2][4];
#pragma unroll
            for (int mi = 0; mi < 4; mi++)
                ldsm_x4(ah[mi], sb + a_off + mi * 16 * LDAh * 2 + kk * 2);
#pragma unroll
            for (int nb = 0; nb < 2; nb++)
                ldsm_x4(bhf[nb], sb + TILEB + b_off + nb * 16 * LDAh * 2 + kk * 2);
#pragma unroll
            for (int nb = 0; nb < 2; nb++)
                ldsm_x4(blf[nb], sb + 2 * TILEB + b_off + nb * 16 * LDAh * 2 + kk * 2);
#pragma unroll
            for (int mi = 0; mi < 4; mi++)
#pragma unroll
                for (int nb = 0; nb < 2; nb++) {
                    mma16816h(acc[mi][nb * 2 + 0], ah[mi], &bhf[nb][0]);
                    mma16816h(acc[mi][nb * 2 + 1], ah[mi], &bhf[nb][2]);
                }
#pragma unroll
            for (int mi = 0; mi < 4; mi++)
#pragma unroll
                for (int nb = 0; nb < 2; nb++) {
                    mma16816h(acc[mi][nb * 2 + 0], ah[mi], &blf[nb][0]);
                    mma16816h(acc[mi][nb * 2 + 1], ah[mi], &blf[nb][2]);
                }
        }

        if (s + 1 < S) {
            char* bb = smc + ((s + 1) & 1) * 3 * TILEB;
#pragma unroll
            for (int i = 0; i < 2; i++) {
                int row = ldrow + i * 64;
                int off = (row * LDAh + ldq * 8) * 2;
                *(uint4*)(bb + off)             = rg[i];
                *(uint4*)(bb + TILEB + off)     = rg[2 + i];
                *(uint4*)(bb + 2 * TILEB + off) = rg[4 + i];
            }
        }
        __syncthreads();
    }

    int frow = lane >> 2;
    int fcol = (lane & 3) * 2;
#pragma unroll
    for (int mi = 0; mi < 4; mi++) {
#pragma unroll
        for (int ni = 0; ni < 4; ni++) {
            int row = m0 + wm * 64 + mi * 16 + frow;
            int col = n0 + wn * 32 + ni * 8 + fcol;
            *(float2*)(C + (size_t)row * N + col) = make_float2(acc[mi][ni][0], acc[mi][ni][1]);
            *(float2*)(C + (size_t)(row + 8) * N + col) = make_float2(acc[mi][ni][2], acc[mi][ni][3]);
        }
    }
}

// ---------------- fp32 -> fp16 convert ----------------
__global__ void tohalf_kernel(const float* __restrict__ src,
                              __half* __restrict__ dst, int n) {
    int i = blockIdx.x * 256 + threadIdx.x;
    if (i < n) dst[i] = __float2half(src[i]);
}

// src [K][N] fp32 -> dst [N][K] fp16 (hi/lo)
__global__ void split_transpose_kernel(const float* __restrict__ src,
                                       __half* __restrict__ hi,
                                       __half* __restrict__ lo,
                                       int K, int N) {
    __shared__ float tile[32][33];
    int k0 = blockIdx.y * 32;
    int n0 = blockIdx.x * 32;
    int tx = threadIdx.x & 31;
    int ty = threadIdx.x >> 5;
    for (int r = ty; r < 32; r += 8) tile[r][tx] = src[(size_t)(k0 + r) * N + n0 + tx];
    __syncthreads();
    for (int r = ty; r < 32; r += 8) {
        float v = tile[tx][r];
        __half h = __float2half(v);
        size_t o = (size_t)(n0 + r) * K + k0 + tx;
        hi[o] = h;
        lo[o] = __float2half(v - __half2float(h));
    }
}

// 4 fused 1024x1024 weight split-transposes
__global__ void split_transpose4_kernel(const float* __restrict__ s0, const float* __restrict__ s1,
                                        const float* __restrict__ s2, const float* __restrict__ s3,
                                        __half* __restrict__ h0, __half* __restrict__ h1,
                                        __half* __restrict__ h2, __half* __restrict__ h3,
                                        __half* __restrict__ l0, __half* __restrict__ l1,
                                        __half* __restrict__ l2, __half* __restrict__ l3) {
    __shared__ float tile[32][33];
    int z = blockIdx.z;
    const float* src = (z == 0) ? s0 : (z == 1) ? s1 : (z == 2) ? s2 : s3;
    __half* hi = (z == 0) ? h0 : (z == 1) ? h1 : (z == 2) ? h2 : h3;
    __half* lo = (z == 0) ? l0 : (z == 1) ? l1 : (z == 2) ? l2 : l3;
    int k0 = blockIdx.y * 32;
    int n0 = blockIdx.x * 32;
    int tx = threadIdx.x & 31;
    int ty = threadIdx.x >> 5;
    for (int r = ty; r < 32; r += 8) tile[r][tx] = src[(size_t)(k0 + r) * 1024 + n0 + tx];
    __syncthreads();
    for (int r = ty; r < 32; r += 8) {
        float v = tile[tx][r];
        __half h = __float2half(v);
        size_t o = (size_t)(n0 + r) * 1024 + k0 + tx;
        hi[o] = h;
        lo[o] = __float2half(v - __half2float(h));
    }
}

// ---------------- beta = sigmoid(x @ Wb) ----------------
__global__ void beta_kernel(const float* __restrict__ x, const float* __restrict__ Wb) {
    int gw   = (blockIdx.x << 3) + (threadIdx.x >> 5);
    int lane = threadIdx.x & 31;
    const float* xr = x + (size_t)gw * HIDv;
    float a0 = 0.f, a1 = 0.f, a2 = 0.f, a3 = 0.f;
    for (int r = lane; r < HIDv; r += 32) {
        float xv = xr[r];
        const float* wb = Wb + r * 4;
        a0 += xv * wb[0]; a1 += xv * wb[1]; a2 += xv * wb[2]; a3 += xv * wb[3];
    }
    for (int o = 16; o; o >>= 1) {
        a0 += __shfl_xor_sync(0xffffffffu, a0, o);
        a1 += __shfl_xor_sync(0xffffffffu, a1, o);
        a2 += __shfl_xor_sync(0xffffffffu, a2, o);
        a3 += __shfl_xor_sync(0xffffffffu, a3, o);
    }
    if (!lane) {
        float* bp = &g_beta[gw * 4];
        bp[0] = 1.f / (1.f + expf(-a0));
        bp[1] = 1.f / (1.f + expf(-a1));
        bp[2] = 1.f / (1.f + expf(-a2));
        bp[3] = 1.f / (1.f + expf(-a3));
    }
}

// ---------------- fused: 3x causal depthwise conv (k=4) + silu ----------------
__global__ void conv3_kernel(const float* __restrict__ qkvlin,
                             const float* __restrict__ w0, float* __restrict__ out0,
                             const float* __restrict__ w1, float* __restrict__ out1,
                             const float* __restrict__ w2, float* __restrict__ out2) {
    int which = blockIdx.x >> 13;
    int bx = blockIdx.x & 8191;
    const float* w = which == 0 ? w0 : (which == 1 ? w1 : w2);
    float* out     = which == 0 ? out0 : (which == 1 ? out1 : out2);
    int idx = bx * 256 + threadIdx.x;
    int c = idx & 1023;
    int l = (idx >> 10) & 1023;
    int b = idx >> 20;
    const float* wc = w + c * 4;
    float acc = 0.f;
#pragma unroll
    for (int j = 0; j < 4; j++) {
        int ls = l - 3 + j;
        if (ls >= 0) acc += qkvlin[((size_t)b * Ll + ls) * 3072 + which * 1024 + c] * wc[j];
    }
    out[idx] = acc / (1.f + expf(-acc));
}

// ---------------- tiled FIR: short (K=3), long (K=31), v copy; writes P + Ph ----------------
// block = (b,h,l-tile of 16); smem v window (46x256) + staged filters
#define FIR_SMEM ((46 * 256 + 31 * 256 + 3 * 256) * 4)   // 81920 B
__global__ __launch_bounds__(256) void fir_tiled_kernel(const float* __restrict__ v,
                                                        const float* __restrict__ fs,
                                                        const float* __restrict__ fl) {
    float* vwin = (float*)dynsm;            // [46][256]
    float* flm  = vwin + 46 * 256;          // [256][31] (d-major)
    float* fsm  = flm + 31 * 256;           // [256][3]

    int t = threadIdx.x;                    // d
    int lt = blockIdx.x & 63;
    int bh = blockIdx.x >> 6;
    int h = bh & 3;
    int b = bh >> 2;
    int l0 = lt * 16;

    // stage filters (coalesced global reads)
    for (int idx = t; idx < 256 * 31; idx += 256) flm[idx] = fl[(size_t)h * 256 * 31 + idx];
    for (int idx = t; idx < 256 * 3; idx += 256)  fsm[idx] = fs[(size_t)h * 256 * 3 + idx];
    // stage v window rows l0-30 .. l0+15
    for (int r = 0; r < 46; r++) {
        int l = l0 - 30 + r;
        vwin[r * 256 + t] = (l >= 0) ? v[(((size_t)b * Ll + l) * NHh + h) * 256 + t] : 0.f;
    }
    __syncthreads();

    const float* myfl = &flm[t * 31];
    const float* myfs = &fsm[t * 3];
    for (int li = 0; li < 16; li++) {
        float accL = 0.f;
#pragma unroll
        for (int j = 0; j < 31; j++) accL += vwin[(li + j) * 256 + t] * myfl[j];
        float accS = vwin[(li + 28) * 256 + t] * myfs[0]
                   + vwin[(li + 29) * 256 + t] * myfs[1]
                   + vwin[(li + 30) * 256 + t] * myfs[2];
        float vcur = vwin[(li + 30) * 256 + t];
        size_t row = ((size_t)b * Ll + l0 + li) * NHh + h;
        g_P [(row * 4 + 0) * 256 + t] = accS;
        g_P [(row * 4 + 1) * 256 + t] = accL;
        g_P [(row * 4 + 3) * 256 + t] = vcur;
        g_Ph[(row * 4 + 0) * 256 + t] = __float2half(accS);
        g_Ph[(row * 4 + 1) * 256 + t] = __float2half(accL);
        g_Ph[(row * 4 + 3) * 256 + t] = __float2half(vcur);
    }
}

// ---------------- delta pre ----------------
__global__ void delta_pre_kernel() {
    float* smf = (float*)dynsm;
    float* qs  = smf;
    float* kn  = qs + 8224;
    float* vb  = kn + 8224;
    float* Am  = vb + 8224;
    float* Tm  = Am + 1024;
    float* bet = Tm + 1056;
    float* rsq = bet + 32;
    float* rsk = rsq + 32;

    int t  = threadIdx.x;
    int n  = blockIdx.x & 31;
    int bh = blockIdx.x >> 5;
    int h  = bh & 3;
    int b  = bh >> 2;
    int l0 = n * CHh;
    size_t gbase = (((size_t)b * Ll + l0) * NHh + h) * 256;
    size_t obase = ((((size_t)b * NHh + h) * NCc + n) * CHh) * 256;

    for (int idx = t; idx < CHh * 256; idx += 256) {
        int c = idx >> 8;
        int d = idx & 255;
        size_t off = gbase + (size_t)c * (NHh * 256) + d;
        qs[c * 257 + d] = g_q[off];
        kn[c * 257 + d] = g_k[off];
        vb[c * 257 + d] = g_v[off];
    }
    if (t < CHh) bet[t] = g_beta[((size_t)b * Ll + l0 + t) * NHh + h];
    __syncthreads();

    int lane = t & 31;
    int wid = t >> 5;
    for (int r = wid; r < CHh; r += 8) {
        float sq = 0.f, sk = 0.f;
        for (int d = lane; d < 256; d += 32) {
            float a = qs[r * 257 + d]; sq += a * a;
            float c2 = kn[r * 257 + d]; sk += c2 * c2;
        }
        for (int o = 16; o; o >>= 1) {
            sq += __shfl_xor_sync(0xffffffffu, sq, o);
            sk += __shfl_xor_sync(0xffffffffu, sk, o);
        }
        if (!lane) { rsq[r] = rsqrtf(sq + 1e-6f); rsk[r] = rsqrtf(sk + 1e-6f); }
    }
    __syncthreads();

    for (int idx = t; idx < CHh * 256; idx += 256) {
        int c = idx >> 8;
        int d = idx & 255;
        float qv = qs[c * 257 + d] * rsq[c]; qs[c * 257 + d] = qv; g_qn[obase + idx] = qv;
        float kv = kn[c * 257 + d] * rsk[c]; kn[c * 257 + d] = kv; g_kn[obase + idx] = kv;
        vb[c * 257 + d] *= bet[c];
    }
    __syncthreads();

    size_t abase = ((((size_t)b * NHh + h) * NCc + n) << 10);
    for (int p = t; p < 1024; p += 256) {
        int i = p >> 5;
        int jj = p & 31;
        float dq = 0.f, dk2 = 0.f;
        if (jj <= i) {
            const float* qi = &qs[i * 257];
            const float* kj = &kn[jj * 257];
            for (int d = 0; d < 256; d++) dq += qi[d] * kj[d];
        }
        if (jj < i) {
            const float* ki = &kn[i * 257];
            const float* kj = &kn[jj * 257];
            for (int d = 0; d < 256; d++) dk2 += ki[d] * kj[d];
        }
        Am[p] = (jj < i) ? (-bet[i] * dk2) : 0.f;
        g_attn[abase + p] = (jj <= i) ? dq : 0.f;
    }
    __syncthreads();

    if (t < 32) {
        Tm[t] = (t == 0) ? 1.f : 0.f;
        for (int i = 1; i < 32; i++) {
            float acc = (i == t) ? 1.f : 0.f;
            for (int m = 0; m < i; m++) acc += Am[i * 32 + m] * Tm[m * 33 + t];
            Tm[i * 33 + t] = acc;
        }
    }
    __syncthreads();

    {
        int d = t;
        for (int r = 0; r < 32; r++) {
            float au = 0.f, aw = 0.f;
            const float* Tr = &Tm[r * 33];
            for (int m = 0; m <= r; m++) {
                float tv = Tr[m];
                au += tv * vb[m * 257 + d];
                aw += tv * bet[m] * kn[m * 257 + d];
            }
            g_u[obase + r * 256 + d] = au;
            g_w[obase + r * 256 + d] = aw;
        }
    }
}

// ---------------- serial chunk scan (writes P slot2 + Ph slot2) ----------------
#define KST 272
__global__ void scan_kernel() {
    float* smf = (float*)dynsm;
    float* S  = smf;
    float* qn = S + 4352;
    float* kn = qn + 8704;
    float* wS = kn + 8704;
    float* un = wS + 8704;
    float* uu = un + 544;
    float* at = uu + 512;

    int t = threadIdx.x;
    int s_idx = blockIdx.x & 15;
    int bh = blockIdx.x >> 4;
    int h = bh & 3;
    int b = bh >> 2;
    int j0 = s_idx * 16;

    for (int i = t; i < 4352; i += 256) S[i] = 0.f;
    __syncthreads();

    int j = t & 15;
    int cg = t >> 4;
    int c0 = cg * 2;
    int c1 = c0 + 1;

    for (int n = 0; n < NCc; n++) {
        size_t base = ((((size_t)b * NHh + h) * NCc + n) * CHh) * 256;
        for (int idx = t; idx < 32 * 64; idx += 256) {
            int c = idx >> 6;
            int dq = (idx & 63) << 2;
            *(float4*)(&qn[c * KST + dq]) = *(const float4*)(&g_qn[base + c * 256 + dq]);
            *(float4*)(&kn[c * KST + dq]) = *(const float4*)(&g_kn[base + c * 256 + dq]);
            *(float4*)(&wS[c * KST + dq]) = *(const float4*)(&g_w [base + c * 256 + dq]);
        }
        for (int idx = t; idx < 512; idx += 256) {
            int c = idx >> 4;
            int jj = idx & 15;
            uu[idx] = g_u[base + c * 256 + j0 + jj];
        }
        size_t abase = ((((size_t)b * NHh + h) * NCc + n) << 10);
        for (int idx = t; idx < 1024; idx += 256) {
            int c = idx >> 5;
            int cp = idx & 31;
            at[c * 33 + cp] = g_attn[abase + idx];
        }
        __syncthreads();

        float a0 = uu[c0 * 16 + j];
        float a1 = uu[c1 * 16 + j];
        float o0 = 0.f, o1 = 0.f;
        const float* w0 = &wS[c0 * KST];
        const float* w1 = &wS[c1 * KST];
        const float* q0 = &qn[c0 * KST];
        const float* q1 = &qn[c1 * KST];
#pragma unroll 8
        for (int d4 = 0; d4 < 64; d4++) {
            int d = d4 << 2;
            float4 wv0 = *(const float4*)(&w0[d]);
            float4 wv1 = *(const float4*)(&w1[d]);
            float4 qv0 = *(const float4*)(&q0[d]);
            float4 qv1 = *(const float4*)(&q1[d]);
            float s0 = S[(d + 0) * 17 + j];
            float s1 = S[(d + 1) * 17 + j];
            float s2 = S[(d + 2) * 17 + j];
            float s3 = S[(d + 3) * 17 + j];
            a0 -= wv0.x * s0 + wv0.y * s1 + wv0.z * s2 + wv0.w * s3;
            a1 -= wv1.x * s0 + wv1.y * s1 + wv1.z * s2 + wv1.w * s3;
            o0 += qv0.x * s0 + qv0.y * s1 + qv0.z * s2 + qv0.w * s3;
            o1 += qv1.x * s0 + qv1.y * s1 + qv1.z * s2 + qv1.w * s3;
        }
        un[c0 * 17 + j] = a0;
        un[c1 * 17 + j] = a1;
        __syncthreads();

        for (int cp = 0; cp <= c0; cp++) o0 += at[c0 * 33 + cp] * un[cp * 17 + j];
        for (int cp = 0; cp <= c1; cp++) o1 += at[c1 * 33 + cp] * un[cp * 17 + j];
        {
            int l = n * CHh;
            size_t r0 = (((size_t)b * Ll + l + c0) * NHh + h) * 4 + 2;
            size_t r1 = (((size_t)b * Ll + l + c1) * NHh + h) * 4 + 2;
            g_P [r0 * 256 + j0 + j] = o0;
            g_P [r1 * 256 + j0 + j] = o1;
            g_Ph[r0 * 256 + j0 + j] = __float2half(o0);
            g_Ph[r1 * 256 + j0 + j] = __float2half(o1);
        }

#pragma unroll
        for (int blk = 0; blk < 4; blk++) {
            int d0 = cg * 16 + blk * 4;
            float s0 = S[(d0 + 0) * 17 + j];
            float s1 = S[(d0 + 1) * 17 + j];
            float s2 = S[(d0 + 2) * 17 + j];
            float s3 = S[(d0 + 3) * 17 + j];
            for (int c = 0; c < 32; c++) {
                float u = un[c * 17 + j];
                float4 kv = *(const float4*)(&kn[c * KST + d0]);
                s0 += kv.x * u; s1 += kv.y * u; s2 += kv.z * u; s3 += kv.w * u;
            }
            S[(d0 + 0) * 17 + j] = s0;
            S[(d0 + 1) * 17 + j] = s1;
            S[(d0 + 2) * 17 + j] = s2;
            S[(d0 + 3) * 17 + j] = s3;
        }
        __syncthreads();
    }
}

// ---------------- gW1 stat-block column sums ----------------
__global__ void ssum_kernel(const float* __restrict__ gW1) {
    int idx = blockIdx.x * 256 + threadIdx.x;
    int s12 = idx / GHh;
    int nn = idx % GHh;
    float a = 0.f;
    const float* base = gW1 + (size_t)(1024 + s12 * 256) * GHh + nn;
    for (int r = 0; r < 256; r++) a += base[(size_t)r * GHh];
    g_ssum[idx] = a;
}

// ---------------- gate finalize (fused stats; writes oh directly) ----------------
__global__ void gate_final_kernel(const float* __restrict__ gb1,
                                  const float* __restrict__ gW2,
                                  const float* __restrict__ gb2,
                                  const float* __restrict__ temp,
                                  const float* __restrict__ epsf,
                                  const float* __restrict__ onw) {
    __shared__ float mid[GHh];
    __shared__ float st[12];
    __shared__ float w4[4];
    __shared__ float red[256];
    __shared__ float rS[256], rQ[256], rM[256];
    int row = blockIdx.x;
    int t = threadIdx.x;
    int h = row & 3;
    int bl = row >> 2;

    // fused per-branch stats: branch jb = t>>6, sub-index s = t&63, 4 elems/thread
    {
        int jb = t >> 6;
        int s = t & 63;
        const float* p = &g_P[((size_t)row * 4 + jb) << 8];
        float sm = 0.f, sq = 0.f, mx = -3.4e38f;
#pragma unroll
        for (int k = 0; k < 4; k++) {
            float v = p[s + 64 * k];
            sm += v; sq += v * v; mx = fmaxf(mx, v);
        }
        rS[t] = sm; rQ[t] = sq; rM[t] = mx;
        __syncthreads();
        for (int str = 32; str >= 1; str >>= 1) {
            if (s < str) {
                rS[t] += rS[t + str];
                rQ[t] += rQ[t + str];
                rM[t] = fmaxf(rM[t], rM[t + str]);
            }
            __syncthreads();
        }
        if (s == 0) {
            st[jb * 3 + 0] = rS[t] * (1.f / 256.f);
            st[jb * 3 + 1] = sqrtf(fmaxf(rQ[t] * (1.f / 256.f), 1e-8f));
            st[jb * 3 + 2] = rM[t];
        }
        __syncthreads();
    }

    for (int nn = t; nn < GHh; nn += 256) {
        float val = g_hid1[(size_t)bl * GHh + nn] + g_bpart[(size_t)row * GHh + nn] + gb1[nn];
#pragma unroll
        for (int s12 = 0; s12 < 12; s12++) val += st[s12] * g_ssum[s12 * GHh + nn];
        mid[nn] = 0.5f * val * (1.f + erff(val * 0.70710678118654752f));
    }
    __syncthreads();

    {
        int o = t & 3;
        float p = 0.f;
        for (int nidx = t >> 2; nidx < GHh; nidx += 64) p += mid[nidx] * gW2[nidx * 4 + o];
        red[t] = p;
    }
    __syncthreads();
    if (t < 4) {
        float lg = gb2[t];
        for (int g = 0; g < 64; g++) lg += red[g * 4 + t];
        red[t] = lg;
    }
    __syncthreads();
    if (t == 0) {
        float tc = fminf(fmaxf(temp[h], 0.2f), 10.f);
        float l0 = red[0] / tc, l1 = red[1] / tc, l2 = red[2] / tc, l3 = red[3] / tc;
        float mx = fmaxf(fmaxf(l0, l1), fmaxf(l2, l3));
        float e0 = expf(l0 - mx), e1 = expf(l1 - mx), e2 = expf(l2 - mx), e3 = expf(l3 - mx);
        float s = e0 + e1 + e2 + e3;
        float w0 = e0 / s, w1 = e1 / s, w2 = e2 / s, w3 = e3 / s;
        float f0 = fminf(fmaxf(epsf[h * 4 + 0], 1e-7f), 0.1f);
        float f1 = fminf(fmaxf(epsf[h * 4 + 1], 1e-7f), 0.1f);
        float f2 = fminf(fmaxf(epsf[h * 4 + 2], 1e-7f), 0.1f);
        float f3 = fminf(fmaxf(epsf[h * 4 + 3], 1e-7f), 0.1f);
        w0 = fmaxf(w0, f0); w1 = fmaxf(w1, f1); w2 = fmaxf(w2, f2); w3 = fmaxf(w3, f3);
        float s2 = w0 + w1 + w2 + w3;
        w4[0] = w0 / s2; w4[1] = w1 / s2; w4[2] = w2 / s2; w4[3] = w3 / s2;
    }
    __syncthreads();

    float od = 0.f;
#pragma unroll
    for (int jj = 0; jj < 4; jj++) od += w4[jj] * g_P[((size_t)row * 4 + jj) * 256 + t];
    red[t] = od * od;
    __syncthreads();
    for (int s = 128; s > 0; s >>= 1) {
        if (t < s) red[t] += red[t + s];
        __syncthreads();
    }
    float ms = red[0] * (1.f / 256.f);
    g_oh[(size_t)bl * HIDv + h * 256 + t] = __float2half(od * rsqrtf(ms + 1e-5f) * onw[t]);
}

// ---------------- host launcher ----------------
static const int PRE_SMEM  = 26848 * 4;
static const int SCAN_SMEM = 32576 * 4;

extern "C" void kernel_launch(void* const* d_in, const int* in_sizes, int n_in,
                              void* d_out, int out_size) {
    const float *x = 0, *Wq = 0, *Wk = 0, *Wv = 0, *Wb = 0, *qc = 0, *kc = 0, *vc = 0;
    const float *firs = 0, *firl = 0, *gW1 = 0, *gb1 = 0, *gW2 = 0, *gb2 = 0;
    const float *temp = 0, *epsf = 0, *onw = 0, *Wo = 0;
    int occ1M = 0, occ4k = 0, occ4 = 0;
    for (int i = 0; i < n_in; i++) {
        const float* p = (const float*)d_in[i];
        switch (in_sizes[i]) {
            case 2097152: x = p; break;
            case 1048576:
                if (occ1M == 0) Wq = p; else if (occ1M == 1) Wk = p;
                else if (occ1M == 2) Wv = p; else Wo = p;
                occ1M++; break;
            case 4096:
                if (occ4k == 0) Wb = p; else if (occ4k == 1) qc = p;
                else if (occ4k == 2) kc = p; else vc = p;
                occ4k++; break;
            case 2621440: gW1 = p; break;
            case 512:     gb1 = p; break;
            case 2048:    gW2 = p; break;
            case 4:       if (occ4 == 0) gb2 = p; else temp = p; occ4++; break;
            case 16:      epsf = p; break;
            case 256:     onw = p; break;
            case 3072:    firs = p; break;
            case 31744:   firl = p; break;
            default: break;
        }
    }

    float *p_qkvlin, *p_q, *p_k, *p_v, *p_hid1, *p_bpart;
    cudaGetSymbolAddress((void**)&p_qkvlin, g_qkvlin);
    cudaGetSymbolAddress((void**)&p_q, g_q);
    cudaGetSymbolAddress((void**)&p_k, g_k);
    cudaGetSymbolAddress((void**)&p_v, g_v);
    cudaGetSymbolAddress((void**)&p_hid1, g_hid1);
    cudaGetSymbolAddress((void**)&p_bpart, g_bpart);

    __half *xh, *Ph, *oh;
    __half *Wqkvh, *Wqkvl, *Woh, *Wol, *g1ah, *g1al, *g1bh, *g1bl;
    cudaGetSymbolAddress((void**)&xh, g_xh);
    cudaGetSymbolAddress((void**)&Ph, g_Ph);
    cudaGetSymbolAddress((void**)&oh, g_oh);
    cudaGetSymbolAddress((void**)&Wqkvh, g_Wqkvh); cudaGetSymbolAddress((void**)&Wqkvl, g_Wqkvl);
    cudaGetSymbolAddress((void**)&Woh, g_Woh);     cudaGetSymbolAddress((void**)&Wol, g_Wol);
    cudaGetSymbolAddress((void**)&g1ah, g_g1ah);   cudaGetSymbolAddress((void**)&g1al, g_g1al);
    cudaGetSymbolAddress((void**)&g1bh, g_g1bh);   cudaGetSymbolAddress((void**)&g1bl, g_g1bl);

    cudaFuncSetAttribute(delta_pre_kernel, cudaFuncAttributeMaxDynamicSharedMemorySize, PRE_SMEM);
    cudaFuncSetAttribute(scan_kernel, cudaFuncAttributeMaxDynamicSharedMemorySize, SCAN_SMEM);
    cudaFuncSetAttribute(gemm_fp16x2, cudaFuncAttributeMaxDynamicSharedMemorySize, GEMM_SMEM);
    cudaFuncSetAttribute(fir_tiled_kernel, cudaFuncAttributeMaxDynamicSharedMemorySize, FIR_SMEM);

    const size_t W1M = (size_t)1024 * 1024;

    // single stream; launch #4 = merged QKV GEMM (profiled)
    tohalf_kernel<<<8192, 256>>>(x, xh, BLr * HIDv);                              // 1
    split_transpose4_kernel<<<dim3(32, 32, 4), 256>>>(Wq, Wk, Wv, Wo,
        Wqkvh, Wqkvh + W1M, Wqkvh + 2 * W1M, Woh,
        Wqkvl, Wqkvl + W1M, Wqkvl + 2 * W1M, Wol);                                // 2
    split_transpose_kernel<<<dim3(16, 32), 256>>>(gW1, g1ah, g1al, 1024, 512);    // 3
    gemm_fp16x2<<<dim3(24, 16), 256, GEMM_SMEM>>>(xh, Wqkvh, Wqkvl, p_qkvlin, 2048, 3072, 1024);  // 4 <- profiled
    split_transpose_kernel<<<dim3(16, 32), 256>>>(gW1 + (size_t)4096 * 512, g1bh, g1bl, 1024, 512);
    ssum_kernel<<<24, 256>>>(gW1);
    beta_kernel<<<256, 256>>>(x, Wb);
    conv3_kernel<<<24576, 256>>>(p_qkvlin, qc, p_q, kc, p_k, vc, p_v);
    delta_pre_kernel<<<256, 256, PRE_SMEM>>>();
    scan_kernel<<<128, 256, SCAN_SMEM>>>();
    fir_tiled_kernel<<<512, 256, FIR_SMEM>>>(p_v, firs, firl);
    gemm_fp16x2<<<dim3(4, 16), 256, GEMM_SMEM>>>(xh, g1ah, g1al, p_hid1, 2048, 512, 1024);
    gemm_fp16x2<<<dim3(4, 64), 256, GEMM_SMEM>>>(Ph, g1bh, g1bl, p_bpart, 8192, 512, 1024);
    gate_final_kernel<<<8192, 256>>>(gb1, gW2, gb2, temp, epsf, onw);
    gemm_fp16x2<<<dim3(8, 16), 256, GEMM_SMEM>>>(oh, Woh, Wol, (float*)d_out, 2048, 1024, 1024);
}

// round 12
// speedup vs baseline: 1.3729x; 1.0505x over previous
#include <cuda_runtime.h>
#include <cuda_fp16.h>
#include <stdint.h>
#include <math.h>

// ---------------- problem constants ----------------
#define Bb   2
#define Ll   1024
#define HIDv 1024
#define NHh  4
#define DKk  256
#define NCc  32
#define CHh  32
#define BLr  2048
#define GHh  512

extern __shared__ char dynsm[];

// ---------------- scratch ----------------
__device__ float g_qkvlin[BLr * 3 * HIDv];
__device__ float g_q[BLr * HIDv];
__device__ float g_k[BLr * HIDv];
__device__ float g_v[BLr * HIDv];
__device__ float g_beta[BLr * NHh];
__device__ float g_qn[BLr * HIDv];
__device__ float g_kn[BLr * HIDv];
__device__ float g_u[BLr * HIDv];
__device__ float g_w[BLr * HIDv];
__device__ float g_attn[Bb * NHh * NCc * CHh * CHh];
__device__ float g_P[BLr * NHh * 4 * DKk];
__device__ float g_ssum[12 * GHh];
__device__ float g_hid1[BLr * GHh];
__device__ float g_bpart[BLr * NHh * GHh];

__device__ __half g_xh[BLr * HIDv];
__device__ __half g_Ph[BLr * NHh * 4 * DKk];
__device__ __half g_oh[BLr * HIDv];
__device__ __half g_Wqkvh[3 * HIDv * HIDv];   // [3072][1024]
__device__ __half g_Woh[HIDv * HIDv];
__device__ __half g_g1ah[GHh * HIDv];
__device__ __half g_g1bh[GHh * HIDv];

// ---------------- PTX helpers ----------------
__device__ __forceinline__ uint32_t smem_u32(const void* p) {
    uint32_t a;
    asm("{ .reg .u64 t; cvta.to.shared.u64 t, %1; cvt.u32.u64 %0, t; }" : "=r"(a) : "l"(p));
    return a;
}
__device__ __forceinline__ void ldsm_x4(uint32_t* r, uint32_t addr) {
    asm volatile("ldmatrix.sync.aligned.m8n8.x4.shared.b16 {%0,%1,%2,%3}, [%4];"
                 : "=r"(r[0]), "=r"(r[1]), "=r"(r[2]), "=r"(r[3]) : "r"(addr));
}
__device__ __forceinline__ void mma16816h(float* d, const uint32_t* a, const uint32_t* b) {
    asm volatile(
        "mma.sync.aligned.m16n8k16.row.col.f32.f16.f16.f32 "
        "{%0,%1,%2,%3}, {%4,%5,%6,%7}, {%8,%9}, {%0,%1,%2,%3};"
        : "+f"(d[0]), "+f"(d[1]), "+f"(d[2]), "+f"(d[3])
        : "r"(a[0]), "r"(a[1]), "r"(a[2]), "r"(a[3]), "r"(b[0]), "r"(b[1]));
}

// ---------------- single-term fp16 HMMA GEMM: C[M,N] = A[M,K] @ Bt[N,K]^T ----------------
// CTA tile 128(m) x 256(n), 8 warps (2m x 4n), warp tile 64x64, k-chunk 32, double buffer.
#define LDAh 40
#define TILEA (128 * LDAh * 2)        // 10240 B
#define TILEBB (256 * LDAh * 2)       // 20480 B
#define STAGEB (TILEA + TILEBB)       // 30720 B
#define GEMM_SMEM (2 * STAGEB)        // 61440 B

__global__ __launch_bounds__(256, 1) void gemm_fp16(
    const __half* __restrict__ A, const __half* __restrict__ B,
    float* __restrict__ C, int M, int N, int K) {
    char* smc = dynsm;
    uint32_t sbase = smem_u32(smc);
    int t = threadIdx.x;
    int lane = t & 31;
    int wid = t >> 5;
    int wm = wid & 1;          // 2 m-groups of 64
    int wn = wid >> 1;         // 4 n-groups of 64
    int m0 = blockIdx.y * 128;
    int n0 = blockIdx.x * 256;

    float acc[4][8][4];
#pragma unroll
    for (int i = 0; i < 4; i++)
#pragma unroll
        for (int j = 0; j < 8; j++)
#pragma unroll
            for (int c = 0; c < 4; c++) acc[i][j][c] = 0.f;

    uint4 rg[6];
    int ldrow = t >> 2;        // 0..63
    int ldq = t & 3;
    int soffA0 = ((ldrow)      * LDAh + ldq * 8) * 2;
    int soffA1 = ((ldrow + 64) * LDAh + ldq * 8) * 2;

    int a_off = ((wm * 64 + (lane & 15)) * LDAh + ((lane >> 4) << 3)) * 2;
    int b_off = ((wn * 64 + (lane & 7) + ((lane >> 4) << 3)) * LDAh + (((lane >> 3) & 1) << 3)) * 2;

    const int S = K / 32;

    {
        size_t ga0 = (size_t)(m0 + ldrow) * K + ldq * 8;
        size_t ga1 = (size_t)(m0 + ldrow + 64) * K + ldq * 8;
        rg[0] = *(const uint4*)(A + ga0);
        rg[1] = *(const uint4*)(A + ga1);
#pragma unroll
        for (int i = 0; i < 4; i++)
            rg[2 + i] = *(const uint4*)(B + (size_t)(n0 + ldrow + i * 64) * K + ldq * 8);
    }
    *(uint4*)(smc + soffA0) = rg[0];
    *(uint4*)(smc + soffA1) = rg[1];
#pragma unroll
    for (int i = 0; i < 4; i++)
        *(uint4*)(smc + TILEA + ((ldrow + i * 64) * LDAh + ldq * 8) * 2) = rg[2 + i];
    __syncthreads();

    for (int s = 0; s < S; s++) {
        int cur = s & 1;
        if (s + 1 < S) {
            int k0 = (s + 1) * 32;
            size_t ga0 = (size_t)(m0 + ldrow) * K + k0 + ldq * 8;
            size_t ga1 = (size_t)(m0 + ldrow + 64) * K + k0 + ldq * 8;
            rg[0] = *(const uint4*)(A + ga0);
            rg[1] = *(const uint4*)(A + ga1);
#pragma unroll
            for (int i = 0; i < 4; i++)
                rg[2 + i] = *(const uint4*)(B + (size_t)(n0 + ldrow + i * 64) * K + k0 + ldq * 8);
        }

        uint32_t sb = sbase + cur * STAGEB;
#pragma unroll
        for (int kk = 0; kk < 32; kk += 16) {
            uint32_t ah[4][4], bf[4][4];
#pragma unroll
            for (int mi = 0; mi < 4; mi++)
                ldsm_x4(ah[mi], sb + a_off + mi * 16 * LDAh * 2 + kk * 2);
#pragma unroll
            for (int nb = 0; nb < 4; nb++)
                ldsm_x4(bf[nb], sb + TILEA + b_off + nb * 16 * LDAh * 2 + kk * 2);
#pragma unroll
            for (int mi = 0; mi < 4; mi++)
#pragma unroll
                for (int nb = 0; nb < 4; nb++) {
                    mma16816h(acc[mi][nb * 2 + 0], ah[mi], &bf[nb][0]);
                    mma16816h(acc[mi][nb * 2 + 1], ah[mi], &bf[nb][2]);
                }
        }

        if (s + 1 < S) {
            char* bb = smc + ((s + 1) & 1) * STAGEB;
            *(uint4*)(bb + soffA0) = rg[0];
            *(uint4*)(bb + soffA1) = rg[1];
#pragma unroll
            for (int i = 0; i < 4; i++)
                *(uint4*)(bb + TILEA + ((ldrow + i * 64) * LDAh + ldq * 8) * 2) = rg[2 + i];
        }
        __syncthreads();
    }

    int frow = lane >> 2;
    int fcol = (lane & 3) * 2;
#pragma unroll
    for (int mi = 0; mi < 4; mi++) {
#pragma unroll
        for (int ni = 0; ni < 8; ni++) {
            int row = m0 + wm * 64 + mi * 16 + frow;
            int col = n0 + wn * 64 + ni * 8 + fcol;
            *(float2*)(C + (size_t)row * N + col) = make_float2(acc[mi][ni][0], acc[mi][ni][1]);
            *(float2*)(C + (size_t)(row + 8) * N + col) = make_float2(acc[mi][ni][2], acc[mi][ni][3]);
        }
    }
}

// ---------------- fp32 -> fp16 convert ----------------
__global__ void tohalf_kernel(const float* __restrict__ src,
                              __half* __restrict__ dst, int n) {
    int i = blockIdx.x * 256 + threadIdx.x;
    if (i < n) dst[i] = __float2half(src[i]);
}

// src [K][N] fp32 -> dst [N][K] fp16
__global__ void htrans_kernel(const float* __restrict__ src,
                              __half* __restrict__ hi, int K, int N) {
    __shared__ float tile[32][33];
    int k0 = blockIdx.y * 32;
    int n0 = blockIdx.x * 32;
    int tx = threadIdx.x & 31;
    int ty = threadIdx.x >> 5;
    for (int r = ty; r < 32; r += 8) tile[r][tx] = src[(size_t)(k0 + r) * N + n0 + tx];
    __syncthreads();
    for (int r = ty; r < 32; r += 8)
        hi[(size_t)(n0 + r) * K + k0 + tx] = __float2half(tile[tx][r]);
}

// 4 fused 1024x1024 weight transposes
__global__ void htrans4_kernel(const float* __restrict__ s0, const float* __restrict__ s1,
                               const float* __restrict__ s2, const float* __restrict__ s3,
                               __half* __restrict__ h0, __half* __restrict__ h1,
                               __half* __restrict__ h2, __half* __restrict__ h3) {
    __shared__ float tile[32][33];
    int z = blockIdx.z;
    const float* src = (z == 0) ? s0 : (z == 1) ? s1 : (z == 2) ? s2 : s3;
    __half* hi = (z == 0) ? h0 : (z == 1) ? h1 : (z == 2) ? h2 : h3;
    int k0 = blockIdx.y * 32;
    int n0 = blockIdx.x * 32;
    int tx = threadIdx.x & 31;
    int ty = threadIdx.x >> 5;
    for (int r = ty; r < 32; r += 8) tile[r][tx] = src[(size_t)(k0 + r) * 1024 + n0 + tx];
    __syncthreads();
    for (int r = ty; r < 32; r += 8)
        hi[(size_t)(n0 + r) * 1024 + k0 + tx] = __float2half(tile[tx][r]);
}

// ---------------- beta = sigmoid(x @ Wb) ----------------
__global__ void beta_kernel(const float* __restrict__ x, const float* __restrict__ Wb) {
    int gw   = (blockIdx.x << 3) + (threadIdx.x >> 5);
    int lane = threadIdx.x & 31;
    const float* xr = x + (size_t)gw * HIDv;
    float a0 = 0.f, a1 = 0.f, a2 = 0.f, a3 = 0.f;
    for (int r = lane; r < HIDv; r += 32) {
        float xv = xr[r];
        const float* wb = Wb + r * 4;
        a0 += xv * wb[0]; a1 += xv * wb[1]; a2 += xv * wb[2]; a3 += xv * wb[3];
    }
    for (int o = 16; o; o >>= 1) {
        a0 += __shfl_xor_sync(0xffffffffu, a0, o);
        a1 += __shfl_xor_sync(0xffffffffu, a1, o);
        a2 += __shfl_xor_sync(0xffffffffu, a2, o);
        a3 += __shfl_xor_sync(0xffffffffu, a3, o);
    }
    if (!lane) {
        float* bp = &g_beta[gw * 4];
        bp[0] = 1.f / (1.f + expf(-a0));
        bp[1] = 1.f / (1.f + expf(-a1));
        bp[2] = 1.f / (1.f + expf(-a2));
        bp[3] = 1.f / (1.f + expf(-a3));
    }
}

// ---------------- fused: 3x causal depthwise conv (k=4) + silu ----------------
__global__ void conv3_kernel(const float* __restrict__ qkvlin,
                             const float* __restrict__ w0, float* __restrict__ out0,
                             const float* __restrict__ w1, float* __restrict__ out1,
                             const float* __restrict__ w2, float* __restrict__ out2) {
    int which = blockIdx.x >> 13;
    int bx = blockIdx.x & 8191;
    const float* w = which == 0 ? w0 : (which == 1 ? w1 : w2);
    float* out     = which == 0 ? out0 : (which == 1 ? out1 : out2);
    int idx = bx * 256 + threadIdx.x;
    int c = idx & 1023;
    int l = (idx >> 10) & 1023;
    int b = idx >> 20;
    const float* wc = w + c * 4;
    float acc = 0.f;
#pragma unroll
    for (int j = 0; j < 4; j++) {
        int ls = l - 3 + j;
        if (ls >= 0) acc += qkvlin[((size_t)b * Ll + ls) * 3072 + which * 1024 + c] * wc[j];
    }
    out[idx] = acc / (1.f + expf(-acc));
}

// ---------------- tiled FIR (writes P + Ph) ----------------
#define FIR_SMEM ((46 * 256 + 31 * 256 + 3 * 256) * 4)
__global__ __launch_bounds__(256) void fir_tiled_kernel(const float* __restrict__ v,
                                                        const float* __restrict__ fs,
                                                        const float* __restrict__ fl) {
    float* vwin = (float*)dynsm;
    float* flm  = vwin + 46 * 256;
    float* fsm  = flm + 31 * 256;

    int t = threadIdx.x;
    int lt = blockIdx.x & 63;
    int bh = blockIdx.x >> 6;
    int h = bh & 3;
    int b = bh >> 2;
    int l0 = lt * 16;

    for (int idx = t; idx < 256 * 31; idx += 256) flm[idx] = fl[(size_t)h * 256 * 31 + idx];
    for (int idx = t; idx < 256 * 3; idx += 256)  fsm[idx] = fs[(size_t)h * 256 * 3 + idx];
    for (int r = 0; r < 46; r++) {
        int l = l0 - 30 + r;
        vwin[r * 256 + t] = (l >= 0) ? v[(((size_t)b * Ll + l) * NHh + h) * 256 + t] : 0.f;
    }
    __syncthreads();

    const float* myfl = &flm[t * 31];
    const float* myfs = &fsm[t * 3];
    for (int li = 0; li < 16; li++) {
        float accL = 0.f;
#pragma unroll
        for (int j = 0; j < 31; j++) accL += vwin[(li + j) * 256 + t] * myfl[j];
        float accS = vwin[(li + 28) * 256 + t] * myfs[0]
                   + vwin[(li + 29) * 256 + t] * myfs[1]
                   + vwin[(li + 30) * 256 + t] * myfs[2];
        float vcur = vwin[(li + 30) * 256 + t];
        size_t row = ((size_t)b * Ll + l0 + li) * NHh + h;
        g_P [(row * 4 + 0) * 256 + t] = accS;
        g_P [(row * 4 + 1) * 256 + t] = accL;
        g_P [(row * 4 + 3) * 256 + t] = vcur;
        g_Ph[(row * 4 + 0) * 256 + t] = __float2half(accS);
        g_Ph[(row * 4 + 1) * 256 + t] = __float2half(accL);
        g_Ph[(row * 4 + 3) * 256 + t] = __float2half(vcur);
    }
}

// ---------------- delta pre ----------------
__global__ void delta_pre_kernel() {
    float* smf = (float*)dynsm;
    float* qs  = smf;
    float* kn  = qs + 8224;
    float* vb  = kn + 8224;
    float* Am  = vb + 8224;
    float* Tm  = Am + 1024;
    float* bet = Tm + 1056;
    float* rsq = bet + 32;
    float* rsk = rsq + 32;

    int t  = threadIdx.x;
    int n  = blockIdx.x & 31;
    int bh = blockIdx.x >> 5;
    int h  = bh & 3;
    int b  = bh >> 2;
    int l0 = n * CHh;
    size_t gbase = (((size_t)b * Ll + l0) * NHh + h) * 256;
    size_t obase = ((((size_t)b * NHh + h) * NCc + n) * CHh) * 256;

    for (int idx = t; idx < CHh * 256; idx += 256) {
        int c = idx >> 8;
        int d = idx & 255;
        size_t off = gbase + (size_t)c * (NHh * 256) + d;
        qs[c * 257 + d] = g_q[off];
        kn[c * 257 + d] = g_k[off];
        vb[c * 257 + d] = g_v[off];
    }
    if (t < CHh) bet[t] = g_beta[((size_t)b * Ll + l0 + t) * NHh + h];
    __syncthreads();

    int lane = t & 31;
    int wid = t >> 5;
    for (int r = wid; r < CHh; r += 8) {
        float sq = 0.f, sk = 0.f;
        for (int d = lane; d < 256; d += 32) {
            float a = qs[r * 257 + d]; sq += a * a;
            float c2 = kn[r * 257 + d]; sk += c2 * c2;
        }
        for (int o = 16; o; o >>= 1) {
            sq += __shfl_xor_sync(0xffffffffu, sq, o);
            sk += __shfl_xor_sync(0xffffffffu, sk, o);
        }
        if (!lane) { rsq[r] = rsqrtf(sq + 1e-6f); rsk[r] = rsqrtf(sk + 1e-6f); }
    }
    __syncthreads();

    for (int idx = t; idx < CHh * 256; idx += 256) {
        int c = idx >> 8;
        int d = idx & 255;
        float qv = qs[c * 257 + d] * rsq[c]; qs[c * 257 + d] = qv; g_qn[obase + idx] = qv;
        float kv = kn[c * 257 + d] * rsk[c]; kn[c * 257 + d] = kv; g_kn[obase + idx] = kv;
        vb[c * 257 + d] *= bet[c];
    }
    __syncthreads();

    size_t abase = ((((size_t)b * NHh + h) * NCc + n) << 10);
    for (int p = t; p < 1024; p += 256) {
        int i = p >> 5;
        int jj = p & 31;
        float dq = 0.f, dk2 = 0.f;
        if (jj <= i) {
            const float* qi = &qs[i * 257];
            const float* kj = &kn[jj * 257];
            for (int d = 0; d < 256; d++) dq += qi[d] * kj[d];
        }
        if (jj < i) {
            const float* ki = &kn[i * 257];
            const float* kj = &kn[jj * 257];
            for (int d = 0; d < 256; d++) dk2 += ki[d] * kj[d];
        }
        Am[p] = (jj < i) ? (-bet[i] * dk2) : 0.f;
        g_attn[abase + p] = (jj <= i) ? dq : 0.f;
    }
    __syncthreads();

    if (t < 32) {
        Tm[t] = (t == 0) ? 1.f : 0.f;
        for (int i = 1; i < 32; i++) {
            float acc = (i == t) ? 1.f : 0.f;
            for (int m = 0; m < i; m++) acc += Am[i * 32 + m] * Tm[m * 33 + t];
            Tm[i * 33 + t] = acc;
        }
    }
    __syncthreads();

    {
        int d = t;
        for (int r = 0; r < 32; r++) {
            float au = 0.f, aw = 0.f;
            const float* Tr = &Tm[r * 33];
            for (int m = 0; m <= r; m++) {
                float tv = Tr[m];
                au += tv * vb[m * 257 + d];
                aw += tv * bet[m] * kn[m * 257 + d];
            }
            g_u[obase + r * 256 + d] = au;
            g_w[obase + r * 256 + d] = aw;
        }
    }
}

// ---------------- serial chunk scan (writes P slot2 + Ph slot2) ----------------
#define KST 272
__global__ void scan_kernel() {
    float* smf = (float*)dynsm;
    float* S  = smf;
    float* qn = S + 4352;
    float* kn = qn + 8704;
    float* wS = kn + 8704;
    float* un = wS + 8704;
    float* uu = un + 544;
    float* at = uu + 512;

    int t = threadIdx.x;
    int s_idx = blockIdx.x & 15;
    int bh = blockIdx.x >> 4;
    int h = bh & 3;
    int b = bh >> 2;
    int j0 = s_idx * 16;

    for (int i = t; i < 4352; i += 256) S[i] = 0.f;
    __syncthreads();

    int j = t & 15;
    int cg = t >> 4;
    int c0 = cg * 2;
    int c1 = c0 + 1;

    for (int n = 0; n < NCc; n++) {
        size_t base = ((((size_t)b * NHh + h) * NCc + n) * CHh) * 256;
        for (int idx = t; idx < 32 * 64; idx += 256) {
            int c = idx >> 6;
            int dq = (idx & 63) << 2;
            *(float4*)(&qn[c * KST + dq]) = *(const float4*)(&g_qn[base + c * 256 + dq]);
            *(float4*)(&kn[c * KST + dq]) = *(const float4*)(&g_kn[base + c * 256 + dq]);
            *(float4*)(&wS[c * KST + dq]) = *(const float4*)(&g_w [base + c * 256 + dq]);
        }
        for (int idx = t; idx < 512; idx += 256) {
            int c = idx >> 4;
            int jj = idx & 15;
            uu[idx] = g_u[base + c * 256 + j0 + jj];
        }
        size_t abase = ((((size_t)b * NHh + h) * NCc + n) << 10);
        for (int idx = t; idx < 1024; idx += 256) {
            int c = idx >> 5;
            int cp = idx & 31;
            at[c * 33 + cp] = g_attn[abase + idx];
        }
        __syncthreads();

        float a0 = uu[c0 * 16 + j];
        float a1 = uu[c1 * 16 + j];
        float o0 = 0.f, o1 = 0.f;
        const float* w0 = &wS[c0 * KST];
        const float* w1 = &wS[c1 * KST];
        const float* q0 = &qn[c0 * KST];
        const float* q1 = &qn[c1 * KST];
#pragma unroll 8
        for (int d4 = 0; d4 < 64; d4++) {
            int d = d4 << 2;
            float4 wv0 = *(const float4*)(&w0[d]);
            float4 wv1 = *(const float4*)(&w1[d]);
            float4 qv0 = *(const float4*)(&q0[d]);
            float4 qv1 = *(const float4*)(&q1[d]);
            float s0 = S[(d + 0) * 17 + j];
            float s1 = S[(d + 1) * 17 + j];
            float s2 = S[(d + 2) * 17 + j];
            float s3 = S[(d + 3) * 17 + j];
            a0 -= wv0.x * s0 + wv0.y * s1 + wv0.z * s2 + wv0.w * s3;
            a1 -= wv1.x * s0 + wv1.y * s1 + wv1.z * s2 + wv1.w * s3;
            o0 += qv0.x * s0 + qv0.y * s1 + qv0.z * s2 + qv0.w * s3;
            o1 += qv1.x * s0 + qv1.y * s1 + qv1.z * s2 + qv1.w * s3;
        }
        un[c0 * 17 + j] = a0;
        un[c1 * 17 + j] = a1;
        __syncthreads();

        for (int cp = 0; cp <= c0; cp++) o0 += at[c0 * 33 + cp] * un[cp * 17 + j];
        for (int cp = 0; cp <= c1; cp++) o1 += at[c1 * 33 + cp] * un[cp * 17 + j];
        {
            int l = n * CHh;
            size_t r0 = (((size_t)b * Ll + l + c0) * NHh + h) * 4 + 2;
            size_t r1 = (((size_t)b * Ll + l + c1) * NHh + h) * 4 + 2;
            g_P [r0 * 256 + j0 + j] = o0;
            g_P [r1 * 256 + j0 + j] = o1;
            g_Ph[r0 * 256 + j0 + j] = __float2half(o0);
            g_Ph[r1 * 256 + j0 + j] = __float2half(o1);
        }

#pragma unroll
        for (int blk = 0; blk < 4; blk++) {
            int d0 = cg * 16 + blk * 4;
            float s0 = S[(d0 + 0) * 17 + j];
            float s1 = S[(d0 + 1) * 17 + j];
            float s2 = S[(d0 + 2) * 17 + j];
            float s3 = S[(d0 + 3) * 17 + j];
            for (int c = 0; c < 32; c++) {
                float u = un[c * 17 + j];
                float4 kv = *(const float4*)(&kn[c * KST + d0]);
                s0 += kv.x * u; s1 += kv.y * u; s2 += kv.z * u; s3 += kv.w * u;
            }
            S[(d0 + 0) * 17 + j] = s0;
            S[(d0 + 1) * 17 + j] = s1;
            S[(d0 + 2) * 17 + j] = s2;
            S[(d0 + 3) * 17 + j] = s3;
        }
        __syncthreads();
    }
}

// ---------------- gW1 stat-block column sums ----------------
__global__ void ssum_kernel(const float* __restrict__ gW1) {
    int idx = blockIdx.x * 256 + threadIdx.x;
    int s12 = idx / GHh;
    int nn = idx % GHh;
    float a = 0.f;
    const float* base = gW1 + (size_t)(1024 + s12 * 256) * GHh + nn;
    for (int r = 0; r < 256; r++) a += base[(size_t)r * GHh];
    g_ssum[idx] = a;
}

// ---------------- gate finalize (fused stats; writes oh) ----------------
__global__ void gate_final_kernel(const float* __restrict__ gb1,
                                  const float* __restrict__ gW2,
                                  const float* __restrict__ gb2,
                                  const float* __restrict__ temp,
                                  const float* __restrict__ epsf,
                                  const float* __restrict__ onw) {
    __shared__ float mid[GHh];
    __shared__ float st[12];
    __shared__ float w4[4];
    __shared__ float red[256];
    __shared__ float rS[256], rQ[256], rM[256];
    int row = blockIdx.x;
    int t = threadIdx.x;
    int h = row & 3;
    int bl = row >> 2;

    {
        int jb = t >> 6;
        int s = t & 63;
        const float* p = &g_P[((size_t)row * 4 + jb) << 8];
        float sm = 0.f, sq = 0.f, mx = -3.4e38f;
#pragma unroll
        for (int k = 0; k < 4; k++) {
            float v = p[s + 64 * k];
            sm += v; sq += v * v; mx = fmaxf(mx, v);
        }
        rS[t] = sm; rQ[t] = sq; rM[t] = mx;
        __syncthreads();
        for (int str = 32; str >= 1; str >>= 1) {
            if (s < str) {
                rS[t] += rS[t + str];
                rQ[t] += rQ[t + str];
                rM[t] = fmaxf(rM[t], rM[t + str]);
            }
            __syncthreads();
        }
        if (s == 0) {
            st[jb * 3 + 0] = rS[t] * (1.f / 256.f);
            st[jb * 3 + 1] = sqrtf(fmaxf(rQ[t] * (1.f / 256.f), 1e-8f));
            st[jb * 3 + 2] = rM[t];
        }
        __syncthreads();
    }

    for (int nn = t; nn < GHh; nn += 256) {
        float val = g_hid1[(size_t)bl * GHh + nn] + g_bpart[(size_t)row * GHh + nn] + gb1[nn];
#pragma unroll
        for (int s12 = 0; s12 < 12; s12++) val += st[s12] * g_ssum[s12 * GHh + nn];
        mid[nn] = 0.5f * val * (1.f + erff(val * 0.70710678118654752f));
    }
    __syncthreads();

    {
        int o = t & 3;
        float p = 0.f;
        for (int nidx = t >> 2; nidx < GHh; nidx += 64) p += mid[nidx] * gW2[nidx * 4 + o];
        red[t] = p;
    }
    __syncthreads();
    if (t < 4) {
        float lg = gb2[t];
        for (int g = 0; g < 64; g++) lg += red[g * 4 + t];
        red[t] = lg;
    }
    __syncthreads();
    if (t == 0) {
        float tc = fminf(fmaxf(temp[h], 0.2f), 10.f);
        float l0 = red[0] / tc, l1 = red[1] / tc, l2 = red[2] / tc, l3 = red[3] / tc;
        float mx = fmaxf(fmaxf(l0, l1), fmaxf(l2, l3));
        float e0 = expf(l0 - mx), e1 = expf(l1 - mx), e2 = expf(l2 - mx), e3 = expf(l3 - mx);
        float s = e0 + e1 + e2 + e3;
        float w0 = e0 / s, w1 = e1 / s, w2 = e2 / s, w3 = e3 / s;
        float f0 = fminf(fmaxf(epsf[h * 4 + 0], 1e-7f), 0.1f);
        float f1 = fminf(fmaxf(epsf[h * 4 + 1], 1e-7f), 0.1f);
        float f2 = fminf(fmaxf(epsf[h * 4 + 2], 1e-7f), 0.1f);
        float f3 = fminf(fmaxf(epsf[h * 4 + 3], 1e-7f), 0.1f);
        w0 = fmaxf(w0, f0); w1 = fmaxf(w1, f1); w2 = fmaxf(w2, f2); w3 = fmaxf(w3, f3);
        float s2 = w0 + w1 + w2 + w3;
        w4[0] = w0 / s2; w4[1] = w1 / s2; w4[2] = w2 / s2; w4[3] = w3 / s2;
    }
    __syncthreads();

    float od = 0.f;
#pragma unroll
    for (int jj = 0; jj < 4; jj++) od += w4[jj] * g_P[((size_t)row * 4 + jj) * 256 + t];
    red[t] = od * od;
    __syncthreads();
    for (int s = 128; s > 0; s >>= 1) {
        if (t < s) red[t] += red[t + s];
        __syncthreads();
    }
    float ms = red[0] * (1.f / 256.f);
    g_oh[(size_t)bl * HIDv + h * 256 + t] = __float2half(od * rsqrtf(ms + 1e-5f) * onw[t]);
}

// ---------------- host launcher ----------------
static const int PRE_SMEM  = 26848 * 4;
static const int SCAN_SMEM = 32576 * 4;

extern "C" void kernel_launch(void* const* d_in, const int* in_sizes, int n_in,
                              void* d_out, int out_size) {
    const float *x = 0, *Wq = 0, *Wk = 0, *Wv = 0, *Wb = 0, *qc = 0, *kc = 0, *vc = 0;
    const float *firs = 0, *firl = 0, *gW1 = 0, *gb1 = 0, *gW2 = 0, *gb2 = 0;
    const float *temp = 0, *epsf = 0, *onw = 0, *Wo = 0;
    int occ1M = 0, occ4k = 0, occ4 = 0;
    for (int i = 0; i < n_in; i++) {
        const float* p = (const float*)d_in[i];
        switch (in_sizes[i]) {
            case 2097152: x = p; break;
            case 1048576:
                if (occ1M == 0) Wq = p; else if (occ1M == 1) Wk = p;
                else if (occ1M == 2) Wv = p; else Wo = p;
                occ1M++; break;
            case 4096:
                if (occ4k == 0) Wb = p; else if (occ4k == 1) qc = p;
                else if (occ4k == 2) kc = p; else vc = p;
                occ4k++; break;
            case 2621440: gW1 = p; break;
            case 512:     gb1 = p; break;
            case 2048:    gW2 = p; break;
            case 4:       if (occ4 == 0) gb2 = p; else temp = p; occ4++; break;
            case 16:      epsf = p; break;
            case 256:     onw = p; break;
            case 3072:    firs = p; break;
            case 31744:   firl = p; break;
            default: break;
        }
    }

    float *p_qkvlin, *p_q, *p_k, *p_v, *p_hid1, *p_bpart;
    cudaGetSymbolAddress((void**)&p_qkvlin, g_qkvlin);
    cudaGetSymbolAddress((void**)&p_q, g_q);
    cudaGetSymbolAddress((void**)&p_k, g_k);
    cudaGetSymbolAddress((void**)&p_v, g_v);
    cudaGetSymbolAddress((void**)&p_hid1, g_hid1);
    cudaGetSymbolAddress((void**)&p_bpart, g_bpart);

    __half *xh, *Ph, *oh, *Wqkvh, *Woh, *g1ah, *g1bh;
    cudaGetSymbolAddress((void**)&xh, g_xh);
    cudaGetSymbolAddress((void**)&Ph, g_Ph);
    cudaGetSymbolAddress((void**)&oh, g_oh);
    cudaGetSymbolAddress((void**)&Wqkvh, g_Wqkvh);
    cudaGetSymbolAddress((void**)&Woh, g_Woh);
    cudaGetSymbolAddress((void**)&g1ah, g_g1ah);
    cudaGetSymbolAddress((void**)&g1bh, g_g1bh);

    cudaFuncSetAttribute(delta_pre_kernel, cudaFuncAttributeMaxDynamicSharedMemorySize, PRE_SMEM);
    cudaFuncSetAttribute(scan_kernel, cudaFuncAttributeMaxDynamicSharedMemorySize, SCAN_SMEM);
    cudaFuncSetAttribute(gemm_fp16, cudaFuncAttributeMaxDynamicSharedMemorySize, GEMM_SMEM);
    cudaFuncSetAttribute(fir_tiled_kernel, cudaFuncAttributeMaxDynamicSharedMemorySize, FIR_SMEM);

    const size_t W1M = (size_t)1024 * 1024;

    // single stream; launch #4 = merged QKV GEMM (profiled)
    tohalf_kernel<<<8192, 256>>>(x, xh, BLr * HIDv);                              // 1
    htrans4_kernel<<<dim3(32, 32, 4), 256>>>(Wq, Wk, Wv, Wo,
        Wqkvh, Wqkvh + W1M, Wqkvh + 2 * W1M, Woh);                                // 2
    htrans_kernel<<<dim3(16, 32), 256>>>(gW1, g1ah, 1024, 512);                   // 3
    gemm_fp16<<<dim3(12, 16), 256, GEMM_SMEM>>>(xh, Wqkvh, p_qkvlin, 2048, 3072, 1024);  // 4 <- profiled
    htrans_kernel<<<dim3(16, 32), 256>>>(gW1 + (size_t)4096 * 512, g1bh, 1024, 512);
    ssum_kernel<<<24, 256>>>(gW1);
    beta_kernel<<<256, 256>>>(x, Wb);
    conv3_kernel<<<24576, 256>>>(p_qkvlin, qc, p_q, kc, p_k, vc, p_v);
    delta_pre_kernel<<<256, 256, PRE_SMEM>>>();
    scan_kernel<<<128, 256, SCAN_SMEM>>>();
    fir_tiled_kernel<<<512, 256, FIR_SMEM>>>(p_v, firs, firl);
    gemm_fp16<<<dim3(2, 16), 256, GEMM_SMEM>>>(xh, g1ah, p_hid1, 2048, 512, 1024);
    gemm_fp16<<<dim3(2, 64), 256, GEMM_SMEM>>>(Ph, g1bh, p_bpart, 8192, 512, 1024);
    gate_final_kernel<<<8192, 256>>>(gb1, gW2, gb2, temp, epsf, onw);
    gemm_fp16<<<dim3(4, 16), 256, GEMM_SMEM>>>(oh, Woh, (float*)d_out, 2048, 1024, 1024);
}

// round 13
// speedup vs baseline: 1.4587x; 1.0625x over previous
#include <cuda_runtime.h>
#include <cuda_fp16.h>
#include <stdint.h>
#include <math.h>

// ---------------- problem constants ----------------
#define Bb   2
#define Ll   1024
#define HIDv 1024
#define NHh  4
#define DKk  256
#define NCc  32
#define CHh  32
#define BLr  2048
#define GHh  512

extern __shared__ char dynsm[];

// ---------------- scratch ----------------
__device__ float g_qkvlin[BLr * 3 * HIDv];
__device__ float g_q[BLr * HIDv];
__device__ float g_k[BLr * HIDv];
__device__ float g_v[BLr * HIDv];
__device__ float g_beta[BLr * NHh];
__device__ float g_qn[BLr * HIDv];
__device__ float g_kn[BLr * HIDv];
__device__ float g_u[BLr * HIDv];
__device__ float g_w[BLr * HIDv];
__device__ float g_attn[Bb * NHh * NCc * CHh * CHh];
__device__ float g_P[BLr * NHh * 4 * DKk];
__device__ float g_ssum[12 * GHh];
__device__ float g_hid1[BLr * GHh];
__device__ float g_bpart[BLr * NHh * GHh];

__device__ __half g_xh[BLr * HIDv];
__device__ __half g_Ph[BLr * NHh * 4 * DKk];
__device__ __half g_oh[BLr * HIDv];
__device__ __half g_Wqkvh[3 * HIDv * HIDv];
__device__ __half g_Woh[HIDv * HIDv];
__device__ __half g_g1ah[GHh * HIDv];
__device__ __half g_g1bh[GHh * HIDv];

// ---------------- PTX helpers ----------------
__device__ __forceinline__ uint32_t smem_u32(const void* p) {
    uint32_t a;
    asm("{ .reg .u64 t; cvta.to.shared.u64 t, %1; cvt.u32.u64 %0, t; }" : "=r"(a) : "l"(p));
    return a;
}
__device__ __forceinline__ void ldsm_x4(uint32_t* r, uint32_t addr) {
    asm volatile("ldmatrix.sync.aligned.m8n8.x4.shared.b16 {%0,%1,%2,%3}, [%4];"
                 : "=r"(r[0]), "=r"(r[1]), "=r"(r[2]), "=r"(r[3]) : "r"(addr));
}
__device__ __forceinline__ void mma16816h(float* d, const uint32_t* a, const uint32_t* b) {
    asm volatile(
        "mma.sync.aligned.m16n8k16.row.col.f32.f16.f16.f32 "
        "{%0,%1,%2,%3}, {%4,%5,%6,%7}, {%8,%9}, {%0,%1,%2,%3};"
        : "+f"(d[0]), "+f"(d[1]), "+f"(d[2]), "+f"(d[3])
        : "r"(a[0]), "r"(a[1]), "r"(a[2]), "r"(a[3]), "r"(b[0]), "r"(b[1]));
}

// ---------------- single-term fp16 HMMA GEMM (R12-proven) ----------------
#define LDAh 40
#define TILEA (128 * LDAh * 2)
#define TILEBB (256 * LDAh * 2)
#define STAGEB (TILEA + TILEBB)
#define GEMM_SMEM (2 * STAGEB)

__global__ __launch_bounds__(256, 1) void gemm_fp16(
    const __half* __restrict__ A, const __half* __restrict__ B,
    float* __restrict__ C, int M, int N, int K) {
    char* smc = dynsm;
    uint32_t sbase = smem_u32(smc);
    int t = threadIdx.x;
    int lane = t & 31;
    int wid = t >> 5;
    int wm = wid & 1;
    int wn = wid >> 1;
    int m0 = blockIdx.y * 128;
    int n0 = blockIdx.x * 256;

    float acc[4][8][4];
#pragma unroll
    for (int i = 0; i < 4; i++)
#pragma unroll
        for (int j = 0; j < 8; j++)
#pragma unroll
            for (int c = 0; c < 4; c++) acc[i][j][c] = 0.f;

    uint4 rg[6];
    int ldrow = t >> 2;
    int ldq = t & 3;
    int soffA0 = ((ldrow)      * LDAh + ldq * 8) * 2;
    int soffA1 = ((ldrow + 64) * LDAh + ldq * 8) * 2;

    int a_off = ((wm * 64 + (lane & 15)) * LDAh + ((lane >> 4) << 3)) * 2;
    int b_off = ((wn * 64 + (lane & 7) + ((lane >> 4) << 3)) * LDAh + (((lane >> 3) & 1) << 3)) * 2;

    const int S = K / 32;

    {
        rg[0] = *(const uint4*)(A + (size_t)(m0 + ldrow) * K + ldq * 8);
        rg[1] = *(const uint4*)(A + (size_t)(m0 + ldrow + 64) * K + ldq * 8);
#pragma unroll
        for (int i = 0; i < 4; i++)
            rg[2 + i] = *(const uint4*)(B + (size_t)(n0 + ldrow + i * 64) * K + ldq * 8);
    }
    *(uint4*)(smc + soffA0) = rg[0];
    *(uint4*)(smc + soffA1) = rg[1];
#pragma unroll
    for (int i = 0; i < 4; i++)
        *(uint4*)(smc + TILEA + ((ldrow + i * 64) * LDAh + ldq * 8) * 2) = rg[2 + i];
    __syncthreads();

    for (int s = 0; s < S; s++) {
        int cur = s & 1;
        if (s + 1 < S) {
            int k0 = (s + 1) * 32;
            rg[0] = *(const uint4*)(A + (size_t)(m0 + ldrow) * K + k0 + ldq * 8);
            rg[1] = *(const uint4*)(A + (size_t)(m0 + ldrow + 64) * K + k0 + ldq * 8);
#pragma unroll
            for (int i = 0; i < 4; i++)
                rg[2 + i] = *(const uint4*)(B + (size_t)(n0 + ldrow + i * 64) * K + k0 + ldq * 8);
        }

        uint32_t sb = sbase + cur * STAGEB;
#pragma unroll
        for (int kk = 0; kk < 32; kk += 16) {
            uint32_t ah[4][4], bf[4][4];
#pragma unroll
            for (int mi = 0; mi < 4; mi++)
                ldsm_x4(ah[mi], sb + a_off + mi * 16 * LDAh * 2 + kk * 2);
#pragma unroll
            for (int nb = 0; nb < 4; nb++)
                ldsm_x4(bf[nb], sb + TILEA + b_off + nb * 16 * LDAh * 2 + kk * 2);
#pragma unroll
            for (int mi = 0; mi < 4; mi++)
#pragma unroll
                for (int nb = 0; nb < 4; nb++) {
                    mma16816h(acc[mi][nb * 2 + 0], ah[mi], &bf[nb][0]);
                    mma16816h(acc[mi][nb * 2 + 1], ah[mi], &bf[nb][2]);
                }
        }

        if (s + 1 < S) {
            char* bb = smc + ((s + 1) & 1) * STAGEB;
            *(uint4*)(bb + soffA0) = rg[0];
            *(uint4*)(bb + soffA1) = rg[1];
#pragma unroll
            for (int i = 0; i < 4; i++)
                *(uint4*)(bb + TILEA + ((ldrow + i * 64) * LDAh + ldq * 8) * 2) = rg[2 + i];
        }
        __syncthreads();
    }

    int frow = lane >> 2;
    int fcol = (lane & 3) * 2;
#pragma unroll
    for (int mi = 0; mi < 4; mi++) {
#pragma unroll
        for (int ni = 0; ni < 8; ni++) {
            int row = m0 + wm * 64 + mi * 16 + frow;
            int col = n0 + wn * 64 + ni * 8 + fcol;
            *(float2*)(C + (size_t)row * N + col) = make_float2(acc[mi][ni][0], acc[mi][ni][1]);
            *(float2*)(C + (size_t)(row + 8) * N + col) = make_float2(acc[mi][ni][2], acc[mi][ni][3]);
        }
    }
}

// ---------------- fp32 -> fp16 convert ----------------
__global__ void tohalf_kernel(const float* __restrict__ src,
                              __half* __restrict__ dst, int n) {
    int i = blockIdx.x * 256 + threadIdx.x;
    if (i < n) dst[i] = __float2half(src[i]);
}

// src [K][N] fp32 -> dst [N][K] fp16
__global__ void htrans_kernel(const float* __restrict__ src,
                              __half* __restrict__ hi, int K, int N) {
    __shared__ float tile[32][33];
    int k0 = blockIdx.y * 32;
    int n0 = blockIdx.x * 32;
    int tx = threadIdx.x & 31;
    int ty = threadIdx.x >> 5;
    for (int r = ty; r < 32; r += 8) tile[r][tx] = src[(size_t)(k0 + r) * N + n0 + tx];
    __syncthreads();
    for (int r = ty; r < 32; r += 8)
        hi[(size_t)(n0 + r) * K + k0 + tx] = __float2half(tile[tx][r]);
}

// 4 fused 1024x1024 weight transposes
__global__ void htrans4_kernel(const float* __restrict__ s0, const float* __restrict__ s1,
                               const float* __restrict__ s2, const float* __restrict__ s3,
                               __half* __restrict__ h0, __half* __restrict__ h1,
                               __half* __restrict__ h2, __half* __restrict__ h3) {
    __shared__ float tile[32][33];
    int z = blockIdx.z;
    const float* src = (z == 0) ? s0 : (z == 1) ? s1 : (z == 2) ? s2 : s3;
    __half* hi = (z == 0) ? h0 : (z == 1) ? h1 : (z == 2) ? h2 : h3;
    int k0 = blockIdx.y * 32;
    int n0 = blockIdx.x * 32;
    int tx = threadIdx.x & 31;
    int ty = threadIdx.x >> 5;
    for (int r = ty; r < 32; r += 8) tile[r][tx] = src[(size_t)(k0 + r) * 1024 + n0 + tx];
    __syncthreads();
    for (int r = ty; r < 32; r += 8)
        hi[(size_t)(n0 + r) * 1024 + k0 + tx] = __float2half(tile[tx][r]);
}

// ---------------- beta = sigmoid(x @ Wb) ----------------
__global__ void beta_kernel(const float* __restrict__ x, const float* __restrict__ Wb) {
    int gw   = (blockIdx.x << 3) + (threadIdx.x >> 5);
    int lane = threadIdx.x & 31;
    const float* xr = x + (size_t)gw * HIDv;
    float a0 = 0.f, a1 = 0.f, a2 = 0.f, a3 = 0.f;
    for (int r = lane; r < HIDv; r += 32) {
        float xv = xr[r];
        const float* wb = Wb + r * 4;
        a0 += xv * wb[0]; a1 += xv * wb[1]; a2 += xv * wb[2]; a3 += xv * wb[3];
    }
    for (int o = 16; o; o >>= 1) {
        a0 += __shfl_xor_sync(0xffffffffu, a0, o);
        a1 += __shfl_xor_sync(0xffffffffu, a1, o);
        a2 += __shfl_xor_sync(0xffffffffu, a2, o);
        a3 += __shfl_xor_sync(0xffffffffu, a3, o);
    }
    if (!lane) {
        float* bp = &g_beta[gw * 4];
        bp[0] = 1.f / (1.f + expf(-a0));
        bp[1] = 1.f / (1.f + expf(-a1));
        bp[2] = 1.f / (1.f + expf(-a2));
        bp[3] = 1.f / (1.f + expf(-a3));
    }
}

// ---------------- fused: 3x causal depthwise conv (k=4) + silu ----------------
__global__ void conv3_kernel(const float* __restrict__ qkvlin,
                             const float* __restrict__ w0, float* __restrict__ out0,
                             const float* __restrict__ w1, float* __restrict__ out1,
                             const float* __restrict__ w2, float* __restrict__ out2) {
    int which = blockIdx.x >> 13;
    int bx = blockIdx.x & 8191;
    const float* w = which == 0 ? w0 : (which == 1 ? w1 : w2);
    float* out     = which == 0 ? out0 : (which == 1 ? out1 : out2);
    int idx = bx * 256 + threadIdx.x;
    int c = idx & 1023;
    int l = (idx >> 10) & 1023;
    int b = idx >> 20;
    const float* wc = w + c * 4;
    float acc = 0.f;
#pragma unroll
    for (int j = 0; j < 4; j++) {
        int ls = l - 3 + j;
        if (ls >= 0) acc += qkvlin[((size_t)b * Ll + ls) * 3072 + which * 1024 + c] * wc[j];
    }
    out[idx] = acc / (1.f + expf(-acc));
}

// ---------------- tiled FIR (writes P + Ph) ----------------
#define FIR_SMEM ((46 * 256 + 31 * 256 + 3 * 256) * 4)
__global__ __launch_bounds__(256) void fir_tiled_kernel(const float* __restrict__ v,
                                                        const float* __restrict__ fs,
                                                        const float* __restrict__ fl) {
    float* vwin = (float*)dynsm;
    float* flm  = vwin + 46 * 256;
    float* fsm  = flm + 31 * 256;

    int t = threadIdx.x;
    int lt = blockIdx.x & 63;
    int bh = blockIdx.x >> 6;
    int h = bh & 3;
    int b = bh >> 2;
    int l0 = lt * 16;

    for (int idx = t; idx < 256 * 31; idx += 256) flm[idx] = fl[(size_t)h * 256 * 31 + idx];
    for (int idx = t; idx < 256 * 3; idx += 256)  fsm[idx] = fs[(size_t)h * 256 * 3 + idx];
    for (int r = 0; r < 46; r++) {
        int l = l0 - 30 + r;
        vwin[r * 256 + t] = (l >= 0) ? v[(((size_t)b * Ll + l) * NHh + h) * 256 + t] : 0.f;
    }
    __syncthreads();

    const float* myfl = &flm[t * 31];
    const float* myfs = &fsm[t * 3];
    for (int li = 0; li < 16; li++) {
        float accL = 0.f;
#pragma unroll
        for (int j = 0; j < 31; j++) accL += vwin[(li + j) * 256 + t] * myfl[j];
        float accS = vwin[(li + 28) * 256 + t] * myfs[0]
                   + vwin[(li + 29) * 256 + t] * myfs[1]
                   + vwin[(li + 30) * 256 + t] * myfs[2];
        float vcur = vwin[(li + 30) * 256 + t];
        size_t row = ((size_t)b * Ll + l0 + li) * NHh + h;
        g_P [(row * 4 + 0) * 256 + t] = accS;
        g_P [(row * 4 + 1) * 256 + t] = accL;
        g_P [(row * 4 + 3) * 256 + t] = vcur;
        g_Ph[(row * 4 + 0) * 256 + t] = __float2half(accS);
        g_Ph[(row * 4 + 1) * 256 + t] = __float2half(accL);
        g_Ph[(row * 4 + 3) * 256 + t] = __float2half(vcur);
    }
}

// ---------------- delta pre (float4 + register-tiled; 2 CTA/SM) ----------------
#define PADP 260
#define PRE_SMEM ((3 * 32 * PADP + 1024 + 1056 + 96) * 4)   // 108544 B

__global__ __launch_bounds__(256) void delta_pre_kernel() {
    float* smf = (float*)dynsm;
    float* qs  = smf;                     // 32*260
    float* kn  = qs + 32 * PADP;
    float* vb  = kn + 32 * PADP;
    float* Am  = vb + 32 * PADP;          // 32*32
    float* Tm  = Am + 1024;               // 32*33
    float* bet = Tm + 1056;
    float* rsq = bet + 32;
    float* rsk = rsq + 32;

    int t  = threadIdx.x;
    int n  = blockIdx.x & 31;
    int bh = blockIdx.x >> 5;
    int h  = bh & 3;
    int b  = bh >> 2;
    int l0 = n * CHh;
    size_t gbase = (((size_t)b * Ll + l0) * NHh + h) * 256;
    size_t obase = ((((size_t)b * NHh + h) * NCc + n) * CHh) * 256;

    // float4 tile loads
    for (int idx = t; idx < 32 * 64; idx += 256) {
        int c = idx >> 6;
        int d = (idx & 63) << 2;
        size_t off = gbase + (size_t)c * (NHh * 256) + d;
        *(float4*)(&qs[c * PADP + d]) = *(const float4*)(&g_q[off]);
        *(float4*)(&kn[c * PADP + d]) = *(const float4*)(&g_k[off]);
        *(float4*)(&vb[c * PADP + d]) = *(const float4*)(&g_v[off]);
    }
    if (t < CHh) bet[t] = g_beta[((size_t)b * Ll + l0 + t) * NHh + h];
    __syncthreads();

    int lane = t & 31;
    int wid = t >> 5;
    for (int r = wid; r < CHh; r += 8) {
        float sq = 0.f, sk = 0.f;
        for (int d = lane; d < 256; d += 32) {
            float a = qs[r * PADP + d]; sq += a * a;
            float c2 = kn[r * PADP + d]; sk += c2 * c2;
        }
        for (int o = 16; o; o >>= 1) {
            sq += __shfl_xor_sync(0xffffffffu, sq, o);
            sk += __shfl_xor_sync(0xffffffffu, sk, o);
        }
        if (!lane) { rsq[r] = rsqrtf(sq + 1e-6f); rsk[r] = rsqrtf(sk + 1e-6f); }
    }
    __syncthreads();

    // normalize + emit qn/kn (float4), scale vb by beta
    for (int idx = t; idx < 32 * 64; idx += 256) {
        int c = idx >> 6;
        int d = (idx & 63) << 2;
        float4 qv = *(float4*)(&qs[c * PADP + d]);
        float4 kv = *(float4*)(&kn[c * PADP + d]);
        float4 vv = *(float4*)(&vb[c * PADP + d]);
        float rq = rsq[c], rk = rsk[c], bb2 = bet[c];
        qv.x *= rq; qv.y *= rq; qv.z *= rq; qv.w *= rq;
        kv.x *= rk; kv.y *= rk; kv.z *= rk; kv.w *= rk;
        vv.x *= bb2; vv.y *= bb2; vv.z *= bb2; vv.w *= bb2;
        *(float4*)(&qs[c * PADP + d]) = qv;
        *(float4*)(&kn[c * PADP + d]) = kv;
        *(float4*)(&vb[c * PADP + d]) = vv;
        *(float4*)(&g_qn[obase + c * 256 + d]) = qv;
        *(float4*)(&g_kn[obase + c * 256 + d]) = kv;
    }
    __syncthreads();

    // attn/A: 2x2 register-tiled float4 dot products
    {
        int ti = t >> 4;          // i in {ti, ti+16}
        int tj = t & 15;          // j in {tj, tj+16}
        const float* qA = &qs[ti * PADP];
        const float* qB = &qs[(ti + 16) * PADP];
        const float* kI0 = &kn[ti * PADP];
        const float* kI1 = &kn[(ti + 16) * PADP];
        const float* kJ0 = &kn[tj * PADP];
        const float* kJ1 = &kn[(tj + 16) * PADP];
        float dq00 = 0.f, dq01 = 0.f, dq10 = 0.f, dq11 = 0.f;
        float dk00 = 0.f, dk01 = 0.f, dk10 = 0.f, dk11 = 0.f;
#pragma unroll 4
        for (int d4 = 0; d4 < 64; d4++) {
            int d = d4 << 2;
            float4 a0 = *(const float4*)(&qA[d]);
            float4 a1 = *(const float4*)(&qB[d]);
            float4 b0 = *(const float4*)(&kJ0[d]);
            float4 b1 = *(const float4*)(&kJ1[d]);
            float4 c0 = *(const float4*)(&kI0[d]);
            float4 c1 = *(const float4*)(&kI1[d]);
            dq00 += a0.x * b0.x; dq00 += a0.y * b0.y; dq00 += a0.z * b0.z; dq00 += a0.w * b0.w;
            dq01 += a0.x * b1.x; dq01 += a0.y * b1.y; dq01 += a0.z * b1.z; dq01 += a0.w * b1.w;
            dq10 += a1.x * b0.x; dq10 += a1.y * b0.y; dq10 += a1.z * b0.z; dq10 += a1.w * b0.w;
            dq11 += a1.x * b1.x; dq11 += a1.y * b1.y; dq11 += a1.z * b1.z; dq11 += a1.w * b1.w;
            dk00 += c0.x * b0.x; dk00 += c0.y * b0.y; dk00 += c0.z * b0.z; dk00 += c0.w * b0.w;
            dk01 += c0.x * b1.x; dk01 += c0.y * b1.y; dk01 += c0.z * b1.z; dk01 += c0.w * b1.w;
            dk10 += c1.x * b0.x; dk10 += c1.y * b0.y; dk10 += c1.z * b0.z; dk10 += c1.w * b0.w;
            dk11 += c1.x * b1.x; dk11 += c1.y * b1.y; dk11 += c1.z * b1.z; dk11 += c1.w * b1.w;
        }
        size_t abase = ((((size_t)b * NHh + h) * NCc + n) << 10);
        int i0 = ti, i1 = ti + 16, j0 = tj, j1 = tj + 16;
        float bi0 = bet[i0], bi1 = bet[i1];
        Am[i0 * 32 + j0] = (j0 < i0) ? (-bi0 * dk00) : 0.f;
        Am[i0 * 32 + j1] = (j1 < i0) ? (-bi0 * dk01) : 0.f;
        Am[i1 * 32 + j0] = (j0 < i1) ? (-bi1 * dk10) : 0.f;
        Am[i1 * 32 + j1] = (j1 < i1) ? (-bi1 * dk11) : 0.f;
        g_attn[abase + i0 * 32 + j0] = (j0 <= i0) ? dq00 : 0.f;
        g_attn[abase + i0 * 32 + j1] = (j1 <= i0) ? dq01 : 0.f;
        g_attn[abase + i1 * 32 + j0] = (j0 <= i1) ? dq10 : 0.f;
        g_attn[abase + i1 * 32 + j1] = (j1 <= i1) ? dq11 : 0.f;
    }
    __syncthreads();

    if (t < 32) {
        Tm[t] = (t == 0) ? 1.f : 0.f;
        for (int i = 1; i < 32; i++) {
            float acc = (i == t) ? 1.f : 0.f;
            for (int m = 0; m < i; m++) acc += Am[i * 32 + m] * Tm[m * 33 + t];
            Tm[i * 33 + t] = acc;
        }
    }
    __syncthreads();

    // u/w: preload rows into registers, triangular broadcast accumulation
    {
        int d = t;
        float vbr[32], knr[32];
#pragma unroll
        for (int m = 0; m < 32; m++) {
            vbr[m] = vb[m * PADP + d];
            knr[m] = kn[m * PADP + d] * bet[m];
        }
#pragma unroll
        for (int r = 0; r < 32; r++) {
            float au = 0.f, aw = 0.f;
#pragma unroll
            for (int m = 0; m < 32; m++) {
                if (m <= r) {
                    float tv = Tm[r * 33 + m];
                    au += tv * vbr[m];
                    aw += tv * knr[m];
                }
            }
            g_u[obase + r * 256 + d] = au;
            g_w[obase + r * 256 + d] = aw;
        }
    }
}

// ---------------- serial chunk scan (writes P slot2 + Ph slot2) ----------------
#define KST 272
__global__ void scan_kernel() {
    float* smf = (float*)dynsm;
    float* S  = smf;
    float* qn = S + 4352;
    float* kn = qn + 8704;
    float* wS = kn + 8704;
    float* un = wS + 8704;
    float* uu = un + 544;
    float* at = uu + 512;

    int t = threadIdx.x;
    int s_idx = blockIdx.x & 15;
    int bh = blockIdx.x >> 4;
    int h = bh & 3;
    int b = bh >> 2;
    int j0 = s_idx * 16;

    for (int i = t; i < 4352; i += 256) S[i] = 0.f;
    __syncthreads();

    int j = t & 15;
    int cg = t >> 4;
    int c0 = cg * 2;
    int c1 = c0 + 1;

    for (int n = 0; n < NCc; n++) {
        size_t base = ((((size_t)b * NHh + h) * NCc + n) * CHh) * 256;
        for (int idx = t; idx < 32 * 64; idx += 256) {
            int c = idx >> 6;
            int dq = (idx & 63) << 2;
            *(float4*)(&qn[c * KST + dq]) = *(const float4*)(&g_qn[base + c * 256 + dq]);
            *(float4*)(&kn[c * KST + dq]) = *(const float4*)(&g_kn[base + c * 256 + dq]);
            *(float4*)(&wS[c * KST + dq]) = *(const float4*)(&g_w [base + c * 256 + dq]);
        }
        for (int idx = t; idx < 512; idx += 256) {
            int c = idx >> 4;
            int jj = idx & 15;
            uu[idx] = g_u[base + c * 256 + j0 + jj];
        }
        size_t abase = ((((size_t)b * NHh + h) * NCc + n) << 10);
        for (int idx = t; idx < 1024; idx += 256) {
            int c = idx >> 5;
            int cp = idx & 31;
            at[c * 33 + cp] = g_attn[abase + idx];
        }
        __syncthreads();

        float a0 = uu[c0 * 16 + j];
        float a1 = uu[c1 * 16 + j];
        float o0 = 0.f, o1 = 0.f;
        const float* w0 = &wS[c0 * KST];
        const float* w1 = &wS[c1 * KST];
        const float* q0 = &qn[c0 * KST];
        const float* q1 = &qn[c1 * KST];
#pragma unroll 8
        for (int d4 = 0; d4 < 64; d4++) {
            int d = d4 << 2;
            float4 wv0 = *(const float4*)(&w0[d]);
            float4 wv1 = *(const float4*)(&w1[d]);
            float4 qv0 = *(const float4*)(&q0[d]);
            float4 qv1 = *(const float4*)(&q1[d]);
            float s0 = S[(d + 0) * 17 + j];
            float s1 = S[(d + 1) * 17 + j];
            float s2 = S[(d + 2) * 17 + j];
            float s3 = S[(d + 3) * 17 + j];
            a0 -= wv0.x * s0 + wv0.y * s1 + wv0.z * s2 + wv0.w * s3;
            a1 -= wv1.x * s0 + wv1.y * s1 + wv1.z * s2 + wv1.w * s3;
            o0 += qv0.x * s0 + qv0.y * s1 + qv0.z * s2 + qv0.w * s3;
            o1 += qv1.x * s0 + qv1.y * s1 + qv1.z * s2 + qv1.w * s3;
        }
        un[c0 * 17 + j] = a0;
        un[c1 * 17 + j] = a1;
        __syncthreads();

        for (int cp = 0; cp <= c0; cp++) o0 += at[c0 * 33 + cp] * un[cp * 17 + j];
        for (int cp = 0; cp <= c1; cp++) o1 += at[c1 * 33 + cp] * un[cp * 17 + j];
        {
            int l = n * CHh;
            size_t r0 = (((size_t)b * Ll + l + c0) * NHh + h) * 4 + 2;
            size_t r1 = (((size_t)b * Ll + l + c1) * NHh + h) * 4 + 2;
            g_P [r0 * 256 + j0 + j] = o0;
            g_P [r1 * 256 + j0 + j] = o1;
            g_Ph[r0 * 256 + j0 + j] = __float2half(o0);
            g_Ph[r1 * 256 + j0 + j] = __float2half(o1);
        }

#pragma unroll
        for (int blk = 0; blk < 4; blk++) {
            int d0 = cg * 16 + blk * 4;
            float s0 = S[(d0 + 0) * 17 + j];
            float s1 = S[(d0 + 1) * 17 + j];
            float s2 = S[(d0 + 2) * 17 + j];
            float s3 = S[(d0 + 3) * 17 + j];
            for (int c = 0; c < 32; c++) {
                float u = un[c * 17 + j];
                float4 kv = *(const float4*)(&kn[c * KST + d0]);
                s0 += kv.x * u; s1 += kv.y * u; s2 += kv.z * u; s3 += kv.w * u;
            }
            S[(d0 + 0) * 17 + j] = s0;
            S[(d0 + 1) * 17 + j] = s1;
            S[(d0 + 2) * 17 + j] = s2;
            S[(d0 + 3) * 17 + j] = s3;
        }
        __syncthreads();
    }
}

// ---------------- gW1 stat-block column sums ----------------
__global__ void ssum_kernel(const float* __restrict__ gW1) {
    int idx = blockIdx.x * 256 + threadIdx.x;
    int s12 = idx / GHh;
    int nn = idx % GHh;
    float a = 0.f;
    const float* base = gW1 + (size_t)(1024 + s12 * 256) * GHh + nn;
    for (int r = 0; r < 256; r++) a += base[(size_t)r * GHh];
    g_ssum[idx] = a;
}

// ---------------- gate finalize (fused stats; writes oh) ----------------
__global__ void gate_final_kernel(const float* __restrict__ gb1,
                                  const float* __restrict__ gW2,
                                  const float* __restrict__ gb2,
                                  const float* __restrict__ temp,
                                  const float* __restrict__ epsf,
                                  const float* __restrict__ onw) {
    __shared__ float mid[GHh];
    __shared__ float st[12];
    __shared__ float w4[4];
    __shared__ float red[256];
    __shared__ float rS[256], rQ[256], rM[256];
    int row = blockIdx.x;
    int t = threadIdx.x;
    int h = row & 3;
    int bl = row >> 2;

    {
        int jb = t >> 6;
        int s = t & 63;
        const float* p = &g_P[((size_t)row * 4 + jb) << 8];
        float sm = 0.f, sq = 0.f, mx = -3.4e38f;
#pragma unroll
        for (int k = 0; k < 4; k++) {
            float v = p[s + 64 * k];
            sm += v; sq += v * v; mx = fmaxf(mx, v);
        }
        rS[t] = sm; rQ[t] = sq; rM[t] = mx;
        __syncthreads();
        for (int str = 32; str >= 1; str >>= 1) {
            if (s < str) {
                rS[t] += rS[t + str];
                rQ[t] += rQ[t + str];
                rM[t] = fmaxf(rM[t], rM[t + str]);
            }
            __syncthreads();
        }
        if (s == 0) {
            st[jb * 3 + 0] = rS[t] * (1.f / 256.f);
            st[jb * 3 + 1] = sqrtf(fmaxf(rQ[t] * (1.f / 256.f), 1e-8f));
            st[jb * 3 + 2] = rM[t];
        }
        __syncthreads();
    }

    for (int nn = t; nn < GHh; nn += 256) {
        float val = g_hid1[(size_t)bl * GHh + nn] + g_bpart[(size_t)row * GHh + nn] + gb1[nn];
#pragma unroll
        for (int s12 = 0; s12 < 12; s12++) val += st[s12] * g_ssum[s12 * GHh + nn];
        mid[nn] = 0.5f * val * (1.f + erff(val * 0.70710678118654752f));
    }
    __syncthreads();

    {
        int o = t & 3;
        float p = 0.f;
        for (int nidx = t >> 2; nidx < GHh; nidx += 64) p += mid[nidx] * gW2[nidx * 4 + o];
        red[t] = p;
    }
    __syncthreads();
    if (t < 4) {
        float lg = gb2[t];
        for (int g = 0; g < 64; g++) lg += red[g * 4 + t];
        red[t] = lg;
    }
    __syncthreads();
    if (t == 0) {
        float tc = fminf(fmaxf(temp[h], 0.2f), 10.f);
        float l0 = red[0] / tc, l1 = red[1] / tc, l2 = red[2] / tc, l3 = red[3] / tc;
        float mx = fmaxf(fmaxf(l0, l1), fmaxf(l2, l3));
        float e0 = expf(l0 - mx), e1 = expf(l1 - mx), e2 = expf(l2 - mx), e3 = expf(l3 - mx);
        float s = e0 + e1 + e2 + e3;
        float w0 = e0 / s, w1 = e1 / s, w2 = e2 / s, w3 = e3 / s;
        float f0 = fminf(fmaxf(epsf[h * 4 + 0], 1e-7f), 0.1f);
        float f1 = fminf(fmaxf(epsf[h * 4 + 1], 1e-7f), 0.1f);
        float f2 = fminf(fmaxf(epsf[h * 4 + 2], 1e-7f), 0.1f);
        float f3 = fminf(fmaxf(epsf[h * 4 + 3], 1e-7f), 0.1f);
        w0 = fmaxf(w0, f0); w1 = fmaxf(w1, f1); w2 = fmaxf(w2, f2); w3 = fmaxf(w3, f3);
        float s2 = w0 + w1 + w2 + w3;
        w4[0] = w0 / s2; w4[1] = w1 / s2; w4[2] = w2 / s2; w4[3] = w3 / s2;
    }
    __syncthreads();

    float od = 0.f;
#pragma unroll
    for (int jj = 0; jj < 4; jj++) od += w4[jj] * g_P[((size_t)row * 4 + jj) * 256 + t];
    red[t] = od * od;
    __syncthreads();
    for (int s = 128; s > 0; s >>= 1) {
        if (t < s) red[t] += red[t + s];
        __syncthreads();
    }
    float ms = red[0] * (1.f / 256.f);
    g_oh[(size_t)bl * HIDv + h * 256 + t] = __float2half(od * rsqrtf(ms + 1e-5f) * onw[t]);
}

// ---------------- host launcher ----------------
static const int SCAN_SMEM = 32576 * 4;

extern "C" void kernel_launch(void* const* d_in, const int* in_sizes, int n_in,
                              void* d_out, int out_size) {
    const float *x = 0, *Wq = 0, *Wk = 0, *Wv = 0, *Wb = 0, *qc = 0, *kc = 0, *vc = 0;
    const float *firs = 0, *firl = 0, *gW1 = 0, *gb1 = 0, *gW2 = 0, *gb2 = 0;
    const float *temp = 0, *epsf = 0, *onw = 0, *Wo = 0;
    int occ1M = 0, occ4k = 0, occ4 = 0;
    for (int i = 0; i < n_in; i++) {
        const float* p = (const float*)d_in[i];
        switch (in_sizes[i]) {
            case 2097152: x = p; break;
            case 1048576:
                if (occ1M == 0) Wq = p; else if (occ1M == 1) Wk = p;
                else if (occ1M == 2) Wv = p; else Wo = p;
                occ1M++; break;
            case 4096:
                if (occ4k == 0) Wb = p; else if (occ4k == 1) qc = p;
                else if (occ4k == 2) kc = p; else vc = p;
                occ4k++; break;
            case 2621440: gW1 = p; break;
            case 512:     gb1 = p; break;
            case 2048:    gW2 = p; break;
            case 4:       if (occ4 == 0) gb2 = p; else temp = p; occ4++; break;
            case 16:      epsf = p; break;
            case 256:     onw = p; break;
            case 3072:    firs = p; break;
            case 31744:   firl = p; break;
            default: break;
        }
    }

    float *p_qkvlin, *p_q, *p_k, *p_v, *p_hid1, *p_bpart;
    cudaGetSymbolAddress((void**)&p_qkvlin, g_qkvlin);
    cudaGetSymbolAddress((void**)&p_q, g_q);
    cudaGetSymbolAddress((void**)&p_k, g_k);
    cudaGetSymbolAddress((void**)&p_v, g_v);
    cudaGetSymbolAddress((void**)&p_hid1, g_hid1);
    cudaGetSymbolAddress((void**)&p_bpart, g_bpart);

    __half *xh, *Ph, *oh, *Wqkvh, *Woh, *g1ah, *g1bh;
    cudaGetSymbolAddress((void**)&xh, g_xh);
    cudaGetSymbolAddress((void**)&Ph, g_Ph);
    cudaGetSymbolAddress((void**)&oh, g_oh);
    cudaGetSymbolAddress((void**)&Wqkvh, g_Wqkvh);
    cudaGetSymbolAddress((void**)&Woh, g_Woh);
    cudaGetSymbolAddress((void**)&g1ah, g_g1ah);
    cudaGetSymbolAddress((void**)&g1bh, g_g1bh);

    cudaFuncSetAttribute(delta_pre_kernel, cudaFuncAttributeMaxDynamicSharedMemorySize, PRE_SMEM);
    cudaFuncSetAttribute(scan_kernel, cudaFuncAttributeMaxDynamicSharedMemorySize, SCAN_SMEM);
    cudaFuncSetAttribute(gemm_fp16, cudaFuncAttributeMaxDynamicSharedMemorySize, GEMM_SMEM);
    cudaFuncSetAttribute(fir_tiled_kernel, cudaFuncAttributeMaxDynamicSharedMemorySize, FIR_SMEM);

    const size_t W1M = (size_t)1024 * 1024;

    // single stream; launch #4 = merged QKV GEMM (profiled)
    tohalf_kernel<<<8192, 256>>>(x, xh, BLr * HIDv);                              // 1
    htrans4_kernel<<<dim3(32, 32, 4), 256>>>(Wq, Wk, Wv, Wo,
        Wqkvh, Wqkvh + W1M, Wqkvh + 2 * W1M, Woh);                                // 2
    htrans_kernel<<<dim3(16, 32), 256>>>(gW1, g1ah, 1024, 512);                   // 3
    gemm_fp16<<<dim3(12, 16), 256, GEMM_SMEM>>>(xh, Wqkvh, p_qkvlin, 2048, 3072, 1024);  // 4 <- profiled
    htrans_kernel<<<dim3(16, 32), 256>>>(gW1 + (size_t)4096 * 512, g1bh, 1024, 512);
    ssum_kernel<<<24, 256>>>(gW1);
    beta_kernel<<<256, 256>>>(x, Wb);
    conv3_kernel<<<24576, 256>>>(p_qkvlin, qc, p_q, kc, p_k, vc, p_v);
    delta_pre_kernel<<<256, 256, PRE_SMEM>>>();
    scan_kernel<<<128, 256, SCAN_SMEM>>>();
    fir_tiled_kernel<<<512, 256, FIR_SMEM>>>(p_v, firs, firl);
    gemm_fp16<<<dim3(2, 16), 256, GEMM_SMEM>>>(xh, g1ah, p_hid1, 2048, 512, 1024);
    gemm_fp16<<<dim3(2, 64), 256, GEMM_SMEM>>>(Ph, g1bh, p_bpart, 8192, 512, 1024);
    gate_final_kernel<<<8192, 256>>>(gb1, gW2, gb2, temp, epsf, onw);
    gemm_fp16<<<dim3(4, 16), 256, GEMM_SMEM>>>(oh, Woh, (float*)d_out, 2048, 1024, 1024);
}